// round 12
// baseline (speedup 1.0000x reference)
#include <cuda_runtime.h>
#include <cuda_bf16.h>
#include <mma.h>
#include <math.h>

using namespace nvcuda;

#define BATCH 8192
#define SDIM  376
#define ADIM  17
#define DIN   393
#define DPAD  416           // padded K: 13 chunks of 32
#define KCH   32
#define NCHK  13
#define H1    400
#define NPAD  448           // padded N (4 col-sets of 112 = 7 frags)
#define SBST  456           // B smem stride (odd multiple of 8 -> conflict-free)
#define SAST  424           // full-K A smem stride
#define H2    300
#define TSTEPS 32
#define CAP2  96
#define W2C   22            // W2 rows cached per chunk in the in-CTA slow path

// smem layout (dynamic): [A 32*424*2 = 27136][B0 29184][B1 29184] = 85504
// epilogue overlay: fp32 stage [0, 58368) ; W2 cache [58368, 85504)
#define SM_A     0
#define SM_B0    27136
#define SM_B1    (27136 + 29184)
#define SM_DYN   (27136 + 2 * 29184)
#define SM_STAGE_BYTES (32 * SBST * 4)     // 58368
#define SM_W2C   SM_STAGE_BYTES

// setup-kernel grid split
#define PACKB   ((DPAD * NPAD) / 1024)     // 182 blocks pack W1 (4 elems/thread)
#define CBLK    ((H1 + 7) / 8)             // 50 blocks compute c_i (warp/row)

// ---------------- static device scratch ----------------
__device__ __align__(16) __nv_bfloat16 g_W1p[(size_t)DPAD * NPAD];
__device__ float g_c[H1];          // c_i = max_j W2[i,j]
__device__ float g_b2max;
__device__ float g_const[ADIM];    // 0.05*tanh(vmax(b3_k))

// ---------------- cp.async helpers ----------------
__device__ __forceinline__ void cp16(void* dst, const void* src) {
    unsigned d = (unsigned)__cvta_generic_to_shared(dst);
    asm volatile("cp.async.cg.shared.global [%0], [%1], 16;\n" :: "r"(d), "l"(src));
}
__device__ __forceinline__ void cp_commit() {
    asm volatile("cp.async.commit_group;\n");
}
template<int N> __device__ __forceinline__ void cp_wait() {
    asm volatile("cp.async.wait_group %0;\n" :: "n"(N));
}

// ---------------- K_setup: pack W1 + constants (one launch) ----------------
__global__ __launch_bounds__(256) void k_setup(const float* __restrict__ W1,
                                               const float* __restrict__ W2,
                                               const float* __restrict__ b2,
                                               const float* __restrict__ b3) {
    int bid = blockIdx.x;
    int tid = threadIdx.x;
    if (bid < PACKB) {
        int e0 = (bid * 256 + tid) * 4;
        int r = e0 / NPAD;
        int c = e0 - r * NPAD;
        __nv_bfloat16 v[4];
        if (r < DIN && c < H1) {
            float4 f = *reinterpret_cast<const float4*>(&W1[(size_t)r * H1 + c]);
            v[0] = __float2bfloat16(f.x); v[1] = __float2bfloat16(f.y);
            v[2] = __float2bfloat16(f.z); v[3] = __float2bfloat16(f.w);
        } else {
            v[0] = v[1] = v[2] = v[3] = __float2bfloat16(0.0f);
        }
        *reinterpret_cast<uint2*>(&g_W1p[e0]) = *reinterpret_cast<uint2*>(v);
        return;
    }
    int lane = tid & 31;
    int w    = tid >> 5;
    if (bid < PACKB + CBLK) {
        int i = (bid - PACKB) * 8 + w;     // one warp per neuron row
        if (i < H1) {
            float mm0 = -3.4e38f, mm1 = -3.4e38f, mm2 = -3.4e38f, mm3 = -3.4e38f;
            const float* row = &W2[(size_t)i * H2];
            int j = lane;
#pragma unroll
            for (int k = 0; k < 2; k++) {
                if (j < H2) mm0 = fmaxf(mm0, row[j]); j += 32;
                if (j < H2) mm1 = fmaxf(mm1, row[j]); j += 32;
                if (j < H2) mm2 = fmaxf(mm2, row[j]); j += 32;
                if (j < H2) mm3 = fmaxf(mm3, row[j]); j += 32;
            }
            if (j < H2) mm0 = fmaxf(mm0, row[j]); j += 32;
            if (j < H2) mm1 = fmaxf(mm1, row[j]);
            float m = fmaxf(fmaxf(mm0, mm1), fmaxf(mm2, mm3));
#pragma unroll
            for (int o = 16; o; o >>= 1) m = fmaxf(m, __shfl_xor_sync(0xffffffffu, m, o));
            if (lane == 0) g_c[i] = m;
        }
        return;
    }
    if (w == 0) {
        float m = -3.4e38f;
        for (int j = lane; j < H2; j += 32) m = fmaxf(m, b2[j]);
#pragma unroll
        for (int o = 16; o; o >>= 1) m = fmaxf(m, __shfl_xor_sync(0xffffffffu, m, o));
        if (lane == 0) g_b2max = m;
    } else if (w == 1) {
        if (lane < ADIM) {
            float b = b3[lane];
            float vmax = (b > 0.0f) ? b : 0.5f * b;   // monotone v3 = b3*(1-2^-t)
            g_const[lane] = 0.05f * tanhf(vmax);
        }
    }
}

// ---------------- K1: fully fused kernel --------------------------------
__global__ __launch_bounds__(256, 2) void k_fused(const float* __restrict__ state,
                                                  const float* __restrict__ action,
                                                  const float* __restrict__ b1,
                                                  const float* __restrict__ W2,
                                                  const float* __restrict__ b2,
                                                  const float* __restrict__ W3,
                                                  const float* __restrict__ b3,
                                                  float* __restrict__ out) {
    extern __shared__ __align__(16) unsigned char sm[];
    __nv_bfloat16* sA  = reinterpret_cast<__nv_bfloat16*>(sm + SM_A);
    __nv_bfloat16* sB0 = reinterpret_cast<__nv_bfloat16*>(sm + SM_B0);
    __nv_bfloat16* sB1 = reinterpret_cast<__nv_bfloat16*>(sm + SM_B1);
    float*    stage   = reinterpret_cast<float*>(sm);           // epilogue overlay
    unsigned* stage_u = reinterpret_cast<unsigned*>(sm);
    float*    s_w2c   = reinterpret_cast<float*>(sm + SM_W2C);  // 22x300 W2 cache

    __shared__ float s_c[H1];
    __shared__ float s_b1[H1];
    __shared__ float s_const[ADIM];
    __shared__ float s_b2max;
    // slow-path scratch
    __shared__ unsigned short s_fire[H1];
    __shared__ unsigned       s_msk[H1];
    __shared__ unsigned       s_mask2[H2];
    __shared__ unsigned short s_list2[TSTEPS][CAP2];
    __shared__ int            s_cnt2[TSTEPS];
    __shared__ unsigned short s_slow[32];
    __shared__ int            s_nslow, s_nf, s_any;

    const int tid  = threadIdx.x;
    const int lane = tid & 31;
    const int w    = tid >> 5;
    const int rg   = w >> 2;
    const int cs   = w & 3;
    const int m0   = blockIdx.x * 32;

    if (tid == 0) s_nslow = 0;

    // ---- hoisted B-load addressing: offsets fixed across chunks ----
    unsigned  boff[7];                 // smem element offsets
    unsigned  goff[7];                 // gmem element offsets within a chunk
    {
#pragma unroll
        for (int rep = 0; rep < 7; rep++) {
            int t2 = tid + rep * 256;
            int r = t2 / 56, p = t2 - r * 56;
            boff[rep] = (unsigned)(r * SBST + 8 * p);
            goff[rep] = (unsigned)(r * NPAD + 8 * p);
        }
    }
    auto load_B = [&](int c, __nv_bfloat16* dst) {
        const __nv_bfloat16* base = g_W1p + (size_t)c * (KCH * NPAD);
#pragma unroll
        for (int rep = 0; rep < 7; rep++)
            cp16(dst + boff[rep], base + goff[rep]);
    };

    load_B(0, sB0);
    cp_commit();

    for (int i = tid; i < H1; i += 256) { s_c[i] = g_c[i]; s_b1[i] = b1[i]; }
    if (tid < ADIM) s_const[tid] = g_const[tid];
    if (tid == 32)  s_b2max = g_b2max;

    // A: load fp32 state/action, convert to bf16 smem (fixed-row indexing)
    {
        const int r = tid >> 3;              // 32 rows, 8 threads per row
        const int l8 = tid & 7;
        const float* srow = state + (size_t)(m0 + r) * SDIM;
        __nv_bfloat16* arow = sA + r * SAST;
        for (int c = l8; c < SDIM; c += 8)
            arow[c] = __float2bfloat16(srow[c]);
        const float* act = action + (size_t)(m0 + r) * ADIM;
        for (int c = l8; c < ADIM; c += 8)
            arow[SDIM + c] = __float2bfloat16(act[c]);
        for (int c = l8; c < DPAD - DIN; c += 8)
            arow[DIN + c] = __float2bfloat16(0.0f);
    }

    wmma::fragment<wmma::accumulator, 16, 16, 16, float> acc[7];
#pragma unroll
    for (int f = 0; f < 7; f++) wmma::fill_fragment(acc[f], 0.0f);

    // ---- single-sync pipelined mainloop ----
    for (int c = 0; c < NCHK; c++) {
        __nv_bfloat16* cur = (c & 1) ? sB1 : sB0;
        __nv_bfloat16* nxt = (c & 1) ? sB0 : sB1;
        cp_wait<0>();
        __syncthreads();                 // buffer c ready; mma(c-1) retired
        if (c + 1 < NCHK) {              // safe: nxt's mma finished pre-sync
            load_B(c + 1, nxt);
            cp_commit();
        }
#pragma unroll
        for (int ks = 0; ks < 2; ks++) {
            wmma::fragment<wmma::matrix_a, 16, 16, 16, __nv_bfloat16, wmma::row_major> afrag;
            wmma::load_matrix_sync(afrag,
                sA + (rg * 16) * SAST + c * KCH + ks * 16, SAST);
#pragma unroll
            for (int f = 0; f < 7; f++) {
                wmma::fragment<wmma::matrix_b, 16, 16, 16, __nv_bfloat16, wmma::row_major> bfrag;
                wmma::load_matrix_sync(bfrag,
                    cur + (ks * 16) * SBST + cs * 112 + f * 16, SBST);
                wmma::mma_sync(acc[f], afrag, bfrag, acc[f]);
            }
        }
    }
    __syncthreads();                     // all mma done before stage overlay

    // ---- epilogue: stage fp32 (overlay), LIF -> word in-place ----
#pragma unroll
    for (int f = 0; f < 7; f++)
        wmma::store_matrix_sync(&stage[(rg * 16) * SBST + cs * 112 + f * 16],
                                acc[f], SBST, wmma::mem_row_major);
    __syncthreads();

    // fixed-row LIF pass: row = tid>>3, 50-column strip per thread
    {
        const int r  = tid >> 3;
        const int l8 = tid & 7;
        float*    srow = stage   + r * SBST;
        unsigned* urow = stage_u + r * SBST;
        const int c0 = l8 * 50;
#pragma unroll 2
        for (int k = 0; k < 50; k++) {
            int c = c0 + k;
            float x = srow[c] + s_b1[c];
            unsigned word = 0u;
            if (x >= 0.999999f) {
                float v = 0.0f;
#pragma unroll
                for (int t = 0; t < TSTEPS; t++) {
                    v = fmaf(x - v, 0.5f, v);
                    if (v >= 1.0f) { word |= (1u << t); v = 0.0f; }
                }
            }
            urow[c] = word;
        }
    }
    __syncthreads();

    // ---- per-row tight bound check ----
#pragma unroll
    for (int rr = 0; rr < 4; rr++) {
        int r = w * 4 + rr;
        int grow = m0 + r;
        float accu = 0.0f;                 // lane = timestep
        for (int ch = 0; ch < 13; ch++) {
            int i = ch * 32 + lane;
            unsigned word = (i < H1) ? stage_u[r * SBST + i] : 0u;
            unsigned bal = __ballot_sync(0xffffffffu, word != 0u);
            while (bal) {
                int b = __ffs(bal) - 1;
                bal &= bal - 1;
                unsigned wb = __shfl_sync(0xffffffffu, word, b);
                float ci = s_c[ch * 32 + b];
                if ((wb >> lane) & 1u) accu += ci;
            }
        }
        float u = s_b2max + accu;
        float vb = 0.0f, vbmax = -3.4e38f;
#pragma unroll
        for (int t = 0; t < TSTEPS; t++) {
            float ut = __shfl_sync(0xffffffffu, u, t);
            vb = 0.5f * (vb + ut);
            vbmax = fmaxf(vbmax, vb);
        }
        if (vbmax < 1.0f) {
            if (lane < ADIM) {
                float o = s_const[lane] + action[(size_t)grow * ADIM + lane];
                out[(size_t)grow * ADIM + lane] = fminf(fmaxf(o, -1.0f), 1.0f);
            }
        } else if (lane == 0) {
            int p = atomicAdd(&s_nslow, 1);
            s_slow[p] = (unsigned short)r;
        }
    }
    __syncthreads();

    // ---- in-CTA exact slow path: W2 prefetched in parallel chunks ----
    int nsl = s_nslow;
    for (int sr = 0; sr < nsl; sr++) {
        int r    = s_slow[sr];
        int grow = m0 + r;

        if (tid == 0) s_any = 0;
        if (w == 0) {
            unsigned lmask = (1u << lane) - 1u;
            int nf = 0;
            for (int ch = 0; ch < 13; ch++) {
                int i = ch * 32 + lane;
                unsigned m = (i < H1) ? stage_u[r * SBST + i] : 0u;
                unsigned bal = __ballot_sync(0xffffffffu, m != 0u);
                int pos = nf + __popc(bal & lmask);
                if (m != 0u) { s_fire[pos] = (unsigned short)i; s_msk[pos] = m; }
                nf += __popc(bal);
            }
            if (lane == 0) s_nf = nf;
        }
        __syncthreads();
        int nf = s_nf;

        float a0[TSTEPS], a1[TSTEPS];
#pragma unroll
        for (int t = 0; t < TSTEPS; t++) { a0[t] = 0.0f; a1[t] = 0.0f; }

        for (int base = 0; base < nf; base += W2C) {
            int n = nf - base; if (n > W2C) n = W2C;
            for (int idx = tid; idx < n * H2; idx += 256) {
                int q = idx / H2;
                int j = idx - q * H2;
                s_w2c[q * H2 + j] = W2[(size_t)s_fire[base + q] * H2 + j];
            }
            __syncthreads();
            if (tid < H2) {
                for (int q = 0; q < n; q++) {
                    float wv = s_w2c[q * H2 + tid];
                    unsigned m = s_msk[base + q];
#pragma unroll
                    for (int t = 0; t < TSTEPS; t++)
                        if ((m >> t) & 1u) a0[t] += wv;
                }
            }
            if (tid + 256 < H2) {
                for (int q = 0; q < n; q++) {
                    float wv = s_w2c[q * H2 + tid + 256];
                    unsigned m = s_msk[base + q];
#pragma unroll
                    for (int t = 0; t < TSTEPS; t++)
                        if ((m >> t) & 1u) a1[t] += wv;
                }
            }
            __syncthreads();
        }

        if (tid < H2) {
            float b2j = b2[tid];
            float v2 = 0.0f;
            unsigned mask2 = 0u;
#pragma unroll
            for (int t = 0; t < TSTEPS; t++) {
                float x2 = b2j + a0[t];
                v2 += (x2 - v2) * 0.5f;
                if (v2 >= 1.0f) { mask2 |= (1u << t); v2 = 0.0f; }
            }
            s_mask2[tid] = mask2;
            if (mask2) atomicOr(&s_any, 1);
        }
        if (tid + 256 < H2) {
            float b2j = b2[tid + 256];
            float v2 = 0.0f;
            unsigned mask2 = 0u;
#pragma unroll
            for (int t = 0; t < TSTEPS; t++) {
                float x2 = b2j + a1[t];
                v2 += (x2 - v2) * 0.5f;
                if (v2 >= 1.0f) { mask2 |= (1u << t); v2 = 0.0f; }
            }
            s_mask2[tid + 256] = mask2;
            if (mask2) atomicOr(&s_any, 1);
        }
        __syncthreads();

        if (s_any == 0) {
            if (tid < ADIM) {
                float o = s_const[tid] + action[(size_t)grow * ADIM + tid];
                out[(size_t)grow * ADIM + tid] = fminf(fmaxf(o, -1.0f), 1.0f);
            }
        } else {
            unsigned lmask = (1u << lane) - 1u;
            for (int t = w; t < TSTEPS; t += 8) {
                int cnt = 0;
                for (int ch = 0; ch * 32 < H2; ch++) {
                    int j = ch * 32 + lane;
                    int pred = 0;
                    if (j < H2) pred = (int)((s_mask2[j] >> t) & 1u);
                    unsigned bal = __ballot_sync(0xffffffffu, pred);
                    int pos = cnt + __popc(bal & lmask);
                    if (pred && pos < CAP2) s_list2[t][pos] = (unsigned short)j;
                    cnt += __popc(bal);
                }
                s_cnt2[t] = cnt < CAP2 ? cnt : CAP2;
            }
            __syncthreads();
            if (tid < ADIM) {
                int k = tid;
                float b3k = b3[k];
                float v3 = 0.0f, vmax = -3.4e38f;
                for (int t = 0; t < TSTEPS; t++) {
                    float x3 = b3k;
                    int n = s_cnt2[t];
                    for (int q = 0; q < n; q++)
                        x3 += W3[s_list2[t][q] * ADIM + k];
                    v3 += (x3 - v3) * 0.5f;
                    vmax = fmaxf(vmax, v3);
                }
                float a2 = 0.05f * tanhf(vmax);
                float o = a2 + action[(size_t)grow * ADIM + k];
                out[(size_t)grow * ADIM + k] = fminf(fmaxf(o, -1.0f), 1.0f);
            }
        }
        __syncthreads();
    }
}

// ---------------- launch ----------------
extern "C" void kernel_launch(void* const* d_in, const int* in_sizes, int n_in,
                              void* d_out, int out_size) {
    (void)in_sizes; (void)n_in; (void)out_size;
    const float* state  = (const float*)d_in[0];
    const float* action = (const float*)d_in[1];
    const float* W1     = (const float*)d_in[2];
    const float* b1     = (const float*)d_in[3];
    const float* W2     = (const float*)d_in[4];
    const float* b2     = (const float*)d_in[5];
    const float* W3     = (const float*)d_in[6];
    const float* b3     = (const float*)d_in[7];
    float* out = (float*)d_out;

    cudaFuncSetAttribute(k_fused, cudaFuncAttributeMaxDynamicSharedMemorySize,
                         SM_DYN);

    k_setup<<<PACKB + CBLK + 1, 256>>>(W1, W2, b2, b3);

    k_fused<<<BATCH / 32, 256, SM_DYN>>>(state, action, b1, W2, b2, W3, b3, out);
}

// round 13
// speedup vs baseline: 1.5095x; 1.5095x over previous
#include <cuda_runtime.h>
#include <cuda_bf16.h>
#include <mma.h>
#include <math.h>

using namespace nvcuda;

#define BATCH 8192
#define SDIM  376
#define ADIM  17
#define DIN   393
#define DPAD  416           // padded K: 13 chunks of 32
#define KCH   32
#define NCHK  13
#define H1    400
#define NPAD  448           // padded N
#define SBST  456           // B smem stride (odd multiple of 8 -> conflict-free)
#define SAST  424           // full-K A smem stride
#define H2    300
#define TSTEPS 32
#define CAP2  96
#define W2C   22            // W2 rows cached per chunk in the in-CTA slow path
#define NT    384           // threads per CTA (12 warps)

// smem layout (dynamic): [A 32*424*2 = 27136][B0 29184][B1 29184] = 85504
// epilogue overlay: fp32 stage [0, 58368) ; W2 cache [58368, 85504)
#define SM_A     0
#define SM_B0    27136
#define SM_B1    (27136 + 29184)
#define SM_DYN   (27136 + 2 * 29184)
#define SM_STAGE_BYTES (32 * SBST * 4)     // 58368
#define SM_W2C   SM_STAGE_BYTES

// setup-kernel grid split
#define PACKB   ((DPAD * NPAD) / 1024)     // 182 blocks pack W1 (4 elems/thread)
#define CBLK    ((H1 + 7) / 8)             // 50 blocks compute c_i (warp/row)

// ---------------- static device scratch ----------------
__device__ __align__(16) __nv_bfloat16 g_W1p[(size_t)DPAD * NPAD];
__device__ float g_c[H1];          // c_i = max_j W2[i,j]
__device__ float g_b2max;
__device__ float g_const[ADIM];    // 0.05*tanh(vmax(b3_k))

// ---------------- cp.async helpers ----------------
__device__ __forceinline__ void cp16(void* dst, const void* src) {
    unsigned d = (unsigned)__cvta_generic_to_shared(dst);
    asm volatile("cp.async.cg.shared.global [%0], [%1], 16;\n" :: "r"(d), "l"(src));
}
__device__ __forceinline__ void cp_commit() {
    asm volatile("cp.async.commit_group;\n");
}
template<int N> __device__ __forceinline__ void cp_wait() {
    asm volatile("cp.async.wait_group %0;\n" :: "n"(N));
}

// ---------------- K_setup: pack W1 + constants (one launch) ----------------
__global__ __launch_bounds__(256) void k_setup(const float* __restrict__ W1,
                                               const float* __restrict__ W2,
                                               const float* __restrict__ b2,
                                               const float* __restrict__ b3) {
    int bid = blockIdx.x;
    int tid = threadIdx.x;
    if (bid < PACKB) {
        int e0 = (bid * 256 + tid) * 4;
        int r = e0 / NPAD;
        int c = e0 - r * NPAD;
        __nv_bfloat16 v[4];
        if (r < DIN && c < H1) {
            float4 f = *reinterpret_cast<const float4*>(&W1[(size_t)r * H1 + c]);
            v[0] = __float2bfloat16(f.x); v[1] = __float2bfloat16(f.y);
            v[2] = __float2bfloat16(f.z); v[3] = __float2bfloat16(f.w);
        } else {
            v[0] = v[1] = v[2] = v[3] = __float2bfloat16(0.0f);
        }
        *reinterpret_cast<uint2*>(&g_W1p[e0]) = *reinterpret_cast<uint2*>(v);
        return;
    }
    int lane = tid & 31;
    int w    = tid >> 5;
    if (bid < PACKB + CBLK) {
        int i = (bid - PACKB) * 8 + w;     // one warp per neuron row
        if (i < H1) {
            float mm0 = -3.4e38f, mm1 = -3.4e38f, mm2 = -3.4e38f, mm3 = -3.4e38f;
            const float* row = &W2[(size_t)i * H2];
            int j = lane;
#pragma unroll
            for (int k = 0; k < 2; k++) {
                if (j < H2) mm0 = fmaxf(mm0, row[j]); j += 32;
                if (j < H2) mm1 = fmaxf(mm1, row[j]); j += 32;
                if (j < H2) mm2 = fmaxf(mm2, row[j]); j += 32;
                if (j < H2) mm3 = fmaxf(mm3, row[j]); j += 32;
            }
            if (j < H2) mm0 = fmaxf(mm0, row[j]); j += 32;
            if (j < H2) mm1 = fmaxf(mm1, row[j]);
            float m = fmaxf(fmaxf(mm0, mm1), fmaxf(mm2, mm3));
#pragma unroll
            for (int o = 16; o; o >>= 1) m = fmaxf(m, __shfl_xor_sync(0xffffffffu, m, o));
            if (lane == 0) g_c[i] = m;
        }
        return;
    }
    if (w == 0) {
        float m = -3.4e38f;
        for (int j = lane; j < H2; j += 32) m = fmaxf(m, b2[j]);
#pragma unroll
        for (int o = 16; o; o >>= 1) m = fmaxf(m, __shfl_xor_sync(0xffffffffu, m, o));
        if (lane == 0) g_b2max = m;
    } else if (w == 1) {
        if (lane < ADIM) {
            float b = b3[lane];
            float vmax = (b > 0.0f) ? b : 0.5f * b;   // monotone v3 = b3*(1-2^-t)
            g_const[lane] = 0.05f * tanhf(vmax);
        }
    }
}

// ---------------- K1: fully fused kernel (12 warps) ----------------------
// warp w: rowgroup rg = w/6 (16 rows), colset cw = w%6 with widths
// {5,5,5,5,4,4} frags of 16 cols => 448 cols total.
__global__ __launch_bounds__(NT, 2) void k_fused(const float* __restrict__ state,
                                                 const float* __restrict__ action,
                                                 const float* __restrict__ b1,
                                                 const float* __restrict__ W2,
                                                 const float* __restrict__ b2,
                                                 const float* __restrict__ W3,
                                                 const float* __restrict__ b3,
                                                 float* __restrict__ out) {
    extern __shared__ __align__(16) unsigned char sm[];
    __nv_bfloat16* sA  = reinterpret_cast<__nv_bfloat16*>(sm + SM_A);
    __nv_bfloat16* sB0 = reinterpret_cast<__nv_bfloat16*>(sm + SM_B0);
    __nv_bfloat16* sB1 = reinterpret_cast<__nv_bfloat16*>(sm + SM_B1);
    float*    stage   = reinterpret_cast<float*>(sm);           // epilogue overlay
    unsigned* stage_u = reinterpret_cast<unsigned*>(sm);
    float*    s_w2c   = reinterpret_cast<float*>(sm + SM_W2C);  // 22x300 W2 cache

    __shared__ float s_c[H1];
    __shared__ float s_b1[H1];
    __shared__ float s_const[ADIM];
    __shared__ float s_b2max;
    // slow-path scratch
    __shared__ unsigned short s_fire[H1];
    __shared__ unsigned       s_msk[H1];
    __shared__ unsigned       s_mask2[H2];
    __shared__ unsigned short s_list2[TSTEPS][CAP2];
    __shared__ int            s_cnt2[TSTEPS];
    __shared__ unsigned short s_slow[32];
    __shared__ int            s_nslow, s_nf, s_any;

    const int tid  = threadIdx.x;
    const int lane = tid & 31;
    const int w    = tid >> 5;             // 0..11
    const int rg   = w / 6;                // 0..1
    const int cw   = w - rg * 6;           // 0..5
    const int nfr  = (cw < 4) ? 5 : 4;     // frags this warp owns
    const int fb   = (cw < 4) ? cw * 5 : 20 + (cw - 4) * 4;   // frag base
    const int m0   = blockIdx.x * 32;

    if (tid == 0) s_nslow = 0;

    auto load_B = [&](int c, __nv_bfloat16* dst) {
        // 32 k-rows x 448 cols -> 1792 cp16 (5 reps, guarded)
#pragma unroll
        for (int rep = 0; rep < 5; rep++) {
            int t2 = tid + rep * NT;
            if (t2 < 1792) {
                int r = t2 / 56, p = t2 - r * 56;
                cp16(dst + r * SBST + 8 * p,
                     &g_W1p[(size_t)(c * KCH + r) * NPAD + 8 * p]);
            }
        }
    };

    load_B(0, sB0);
    cp_commit();

    for (int i = tid; i < H1; i += NT) { s_c[i] = g_c[i]; s_b1[i] = b1[i]; }
    if (tid < ADIM) s_const[tid] = g_const[tid];
    if (tid == 32)  s_b2max = g_b2max;

    // A: load fp32 state/action, convert to bf16 smem (32 x 416, stride 424)
    for (int idx = tid; idx < 32 * SDIM; idx += NT) {
        int r = idx / SDIM, c = idx - r * SDIM;
        sA[r * SAST + c] = __float2bfloat16(state[(size_t)(m0 + r) * SDIM + c]);
    }
    for (int idx = tid; idx < 32 * ADIM; idx += NT) {
        int r = idx / ADIM, c = idx - r * ADIM;
        sA[r * SAST + SDIM + c] = __float2bfloat16(action[(size_t)(m0 + r) * ADIM + c]);
    }
    for (int idx = tid; idx < 32 * (DPAD - DIN); idx += NT) {
        int r = idx / (DPAD - DIN), c = idx - r * (DPAD - DIN);
        sA[r * SAST + DIN + c] = __float2bfloat16(0.0f);
    }

    wmma::fragment<wmma::accumulator, 16, 16, 16, float> acc[5];
#pragma unroll
    for (int f = 0; f < 5; f++) wmma::fill_fragment(acc[f], 0.0f);

    // ---- proven R11 mainloop structure ----
    for (int c = 0; c < NCHK; c++) {
        __nv_bfloat16* cur = (c & 1) ? sB1 : sB0;
        __nv_bfloat16* nxt = (c & 1) ? sB0 : sB1;
        if (c + 1 < NCHK) {
            load_B(c + 1, nxt);
            cp_commit();
            cp_wait<1>();
        } else {
            cp_wait<0>();
        }
        __syncthreads();

#pragma unroll
        for (int ks = 0; ks < 2; ks++) {
            wmma::fragment<wmma::matrix_a, 16, 16, 16, __nv_bfloat16, wmma::row_major> afrag;
            wmma::load_matrix_sync(afrag,
                sA + (rg * 16) * SAST + c * KCH + ks * 16, SAST);
#pragma unroll
            for (int f = 0; f < 5; f++) {
                if (f < nfr) {
                    wmma::fragment<wmma::matrix_b, 16, 16, 16, __nv_bfloat16, wmma::row_major> bfrag;
                    wmma::load_matrix_sync(bfrag,
                        cur + (ks * 16) * SBST + (fb + f) * 16, SBST);
                    wmma::mma_sync(acc[f], afrag, bfrag, acc[f]);
                }
            }
        }
        __syncthreads();
    }

    // ---- epilogue: stage fp32 (overlay), LIF -> word in-place ----
#pragma unroll
    for (int f = 0; f < 5; f++)
        if (f < nfr)
            wmma::store_matrix_sync(&stage[(rg * 16) * SBST + (fb + f) * 16],
                                    acc[f], SBST, wmma::mem_row_major);
    __syncthreads();

    for (int idx = tid; idx < 32 * H1; idx += NT) {
        int r = idx / H1;
        int c = idx - r * H1;
        float x = stage[r * SBST + c] + s_b1[c];
        unsigned word = 0u;
        if (x >= 0.999999f) {
            float v = 0.0f;
#pragma unroll
            for (int t = 0; t < TSTEPS; t++) {
                v = fmaf(x - v, 0.5f, v);
                if (v >= 1.0f) { word |= (1u << t); v = 0.0f; }
            }
        }
        stage_u[r * SBST + c] = word;
    }
    __syncthreads();

    // ---- per-row tight bound check: warp w handles rows w, w+12, w+24 ----
    for (int r = w; r < 32; r += 12) {
        int grow = m0 + r;
        float accu = 0.0f;                 // lane = timestep
        for (int ch = 0; ch < 13; ch++) {
            int i = ch * 32 + lane;
            unsigned word = (i < H1) ? stage_u[r * SBST + i] : 0u;
            unsigned bal = __ballot_sync(0xffffffffu, word != 0u);
            while (bal) {
                int b = __ffs(bal) - 1;
                bal &= bal - 1;
                unsigned wb = __shfl_sync(0xffffffffu, word, b);
                float ci = s_c[ch * 32 + b];
                if ((wb >> lane) & 1u) accu += ci;
            }
        }
        float u = s_b2max + accu;
        float vb = 0.0f, vbmax = -3.4e38f;
#pragma unroll
        for (int t = 0; t < TSTEPS; t++) {
            float ut = __shfl_sync(0xffffffffu, u, t);
            vb = 0.5f * (vb + ut);
            vbmax = fmaxf(vbmax, vb);
        }
        if (vbmax < 1.0f) {
            if (lane < ADIM) {
                float o = s_const[lane] + action[(size_t)grow * ADIM + lane];
                out[(size_t)grow * ADIM + lane] = fminf(fmaxf(o, -1.0f), 1.0f);
            }
        } else if (lane == 0) {
            int p = atomicAdd(&s_nslow, 1);
            s_slow[p] = (unsigned short)r;
        }
    }
    __syncthreads();

    // ---- in-CTA exact slow path: W2 prefetched in parallel chunks ----
    int nsl = s_nslow;
    for (int sr = 0; sr < nsl; sr++) {
        int r    = s_slow[sr];
        int grow = m0 + r;

        if (tid == 0) s_any = 0;
        if (w == 0) {
            unsigned lmask = (1u << lane) - 1u;
            int nf = 0;
            for (int ch = 0; ch < 13; ch++) {
                int i = ch * 32 + lane;
                unsigned m = (i < H1) ? stage_u[r * SBST + i] : 0u;
                unsigned bal = __ballot_sync(0xffffffffu, m != 0u);
                int pos = nf + __popc(bal & lmask);
                if (m != 0u) { s_fire[pos] = (unsigned short)i; s_msk[pos] = m; }
                nf += __popc(bal);
            }
            if (lane == 0) s_nf = nf;
        }
        __syncthreads();
        int nf = s_nf;

        // exact layer 2: single j-pass (384 >= 300); W2 via smem chunks
        float a0[TSTEPS];
#pragma unroll
        for (int t = 0; t < TSTEPS; t++) a0[t] = 0.0f;

        for (int base = 0; base < nf; base += W2C) {
            int n = nf - base; if (n > W2C) n = W2C;
            for (int idx = tid; idx < n * H2; idx += NT) {
                int q = idx / H2;
                int j = idx - q * H2;
                s_w2c[q * H2 + j] = W2[(size_t)s_fire[base + q] * H2 + j];
            }
            __syncthreads();
            if (tid < H2) {
                for (int q = 0; q < n; q++) {
                    float wv = s_w2c[q * H2 + tid];
                    unsigned m = s_msk[base + q];
#pragma unroll
                    for (int t = 0; t < TSTEPS; t++)
                        if ((m >> t) & 1u) a0[t] += wv;
                }
            }
            __syncthreads();
        }

        if (tid < H2) {
            float b2j = b2[tid];
            float v2 = 0.0f;
            unsigned mask2 = 0u;
#pragma unroll
            for (int t = 0; t < TSTEPS; t++) {
                float x2 = b2j + a0[t];
                v2 += (x2 - v2) * 0.5f;
                if (v2 >= 1.0f) { mask2 |= (1u << t); v2 = 0.0f; }
            }
            s_mask2[tid] = mask2;
            if (mask2) atomicOr(&s_any, 1);
        }
        __syncthreads();

        if (s_any == 0) {
            if (tid < ADIM) {
                float o = s_const[tid] + action[(size_t)grow * ADIM + tid];
                out[(size_t)grow * ADIM + tid] = fminf(fmaxf(o, -1.0f), 1.0f);
            }
        } else {
            unsigned lmask = (1u << lane) - 1u;
            for (int t = w; t < TSTEPS; t += 12) {
                int cnt = 0;
                for (int ch = 0; ch * 32 < H2; ch++) {
                    int j = ch * 32 + lane;
                    int pred = 0;
                    if (j < H2) pred = (int)((s_mask2[j] >> t) & 1u);
                    unsigned bal = __ballot_sync(0xffffffffu, pred);
                    int pos = cnt + __popc(bal & lmask);
                    if (pred && pos < CAP2) s_list2[t][pos] = (unsigned short)j;
                    cnt += __popc(bal);
                }
                s_cnt2[t] = cnt < CAP2 ? cnt : CAP2;
            }
            __syncthreads();
            if (tid < ADIM) {
                int k = tid;
                float b3k = b3[k];
                float v3 = 0.0f, vmax = -3.4e38f;
                for (int t = 0; t < TSTEPS; t++) {
                    float x3 = b3k;
                    int n = s_cnt2[t];
                    for (int q = 0; q < n; q++)
                        x3 += W3[s_list2[t][q] * ADIM + k];
                    v3 += (x3 - v3) * 0.5f;
                    vmax = fmaxf(vmax, v3);
                }
                float a2 = 0.05f * tanhf(vmax);
                float o = a2 + action[(size_t)grow * ADIM + k];
                out[(size_t)grow * ADIM + k] = fminf(fmaxf(o, -1.0f), 1.0f);
            }
        }
        __syncthreads();
    }
}

// ---------------- launch ----------------
extern "C" void kernel_launch(void* const* d_in, const int* in_sizes, int n_in,
                              void* d_out, int out_size) {
    (void)in_sizes; (void)n_in; (void)out_size;
    const float* state  = (const float*)d_in[0];
    const float* action = (const float*)d_in[1];
    const float* W1     = (const float*)d_in[2];
    const float* b1     = (const float*)d_in[3];
    const float* W2     = (const float*)d_in[4];
    const float* b2     = (const float*)d_in[5];
    const float* W3     = (const float*)d_in[6];
    const float* b3     = (const float*)d_in[7];
    float* out = (float*)d_out;

    cudaFuncSetAttribute(k_fused, cudaFuncAttributeMaxDynamicSharedMemorySize,
                         SM_DYN);

    k_setup<<<PACKB + CBLK + 1, 256>>>(W1, W2, b2, b3);

    k_fused<<<BATCH / 32, NT, SM_DYN>>>(state, action, b1, W2, b2, W3, b3, out);
}

// round 14
// speedup vs baseline: 1.7370x; 1.1507x over previous
#include <cuda_runtime.h>
#include <cuda_bf16.h>
#include <mma.h>
#include <math.h>

using namespace nvcuda;

#define BATCH 8192
#define SDIM  376
#define ADIM  17
#define DIN   393
#define DPAD  416           // padded K: 13 chunks of 32
#define KCH   32
#define NCHK  13
#define H1    400
#define NPAD  448           // padded N
#define SBST  456           // B smem stride (odd multiple of 8 -> conflict-free)
#define SAST  424           // full-K A smem stride
#define H2    300
#define TSTEPS 32
#define CAP2  96
#define W2C   22            // W2 rows cached per chunk in the in-CTA slow path
#define NT    384           // threads per CTA (12 warps)
#define SPCAP 2048          // spike-candidate list capacity (exp ~512)

// smem layout (dynamic): [A 32*424*2 = 27136][B0 29184][B1 29184] = 85504
// epilogue overlay: fp32 stage [0, 58368) ; W2 cache [58368, 85504)
#define SM_A     0
#define SM_B0    27136
#define SM_B1    (27136 + 29184)
#define SM_DYN   (27136 + 2 * 29184)
#define SM_STAGE_BYTES (32 * SBST * 4)     // 58368
#define SM_W2C   SM_STAGE_BYTES

// setup-kernel grid split
#define PACKB   ((DPAD * NPAD) / 1024)     // 182 blocks pack W1 (4 elems/thread)
#define CBLK    ((H1 + 7) / 8)             // 50 blocks compute c_i (warp/row)

// ---------------- static device scratch ----------------
__device__ __align__(16) __nv_bfloat16 g_W1p[(size_t)DPAD * NPAD];
__device__ float g_c[H1];          // c_i = max_j W2[i,j]
__device__ float g_b2max;
__device__ float g_const[ADIM];    // 0.05*tanh(vmax(b3_k))

// ---------------- cp.async helpers ----------------
__device__ __forceinline__ void cp16(void* dst, const void* src) {
    unsigned d = (unsigned)__cvta_generic_to_shared(dst);
    asm volatile("cp.async.cg.shared.global [%0], [%1], 16;\n" :: "r"(d), "l"(src));
}
__device__ __forceinline__ void cp_commit() {
    asm volatile("cp.async.commit_group;\n");
}
template<int N> __device__ __forceinline__ void cp_wait() {
    asm volatile("cp.async.wait_group %0;\n" :: "n"(N));
}

// ---------------- K_setup: pack W1 + constants (one launch) ----------------
__global__ __launch_bounds__(256) void k_setup(const float* __restrict__ W1,
                                               const float* __restrict__ W2,
                                               const float* __restrict__ b2,
                                               const float* __restrict__ b3) {
    int bid = blockIdx.x;
    int tid = threadIdx.x;
    if (bid < PACKB) {
        int e0 = (bid * 256 + tid) * 4;
        int r = e0 / NPAD;
        int c = e0 - r * NPAD;
        __nv_bfloat16 v[4];
        if (r < DIN && c < H1) {
            float4 f = *reinterpret_cast<const float4*>(&W1[(size_t)r * H1 + c]);
            v[0] = __float2bfloat16(f.x); v[1] = __float2bfloat16(f.y);
            v[2] = __float2bfloat16(f.z); v[3] = __float2bfloat16(f.w);
        } else {
            v[0] = v[1] = v[2] = v[3] = __float2bfloat16(0.0f);
        }
        *reinterpret_cast<uint2*>(&g_W1p[e0]) = *reinterpret_cast<uint2*>(v);
        return;
    }
    int lane = tid & 31;
    int w    = tid >> 5;
    if (bid < PACKB + CBLK) {
        int i = (bid - PACKB) * 8 + w;     // one warp per neuron row
        if (i < H1) {
            float mm0 = -3.4e38f, mm1 = -3.4e38f, mm2 = -3.4e38f, mm3 = -3.4e38f;
            const float* row = &W2[(size_t)i * H2];
            int j = lane;
#pragma unroll
            for (int k = 0; k < 2; k++) {
                if (j < H2) mm0 = fmaxf(mm0, row[j]); j += 32;
                if (j < H2) mm1 = fmaxf(mm1, row[j]); j += 32;
                if (j < H2) mm2 = fmaxf(mm2, row[j]); j += 32;
                if (j < H2) mm3 = fmaxf(mm3, row[j]); j += 32;
            }
            if (j < H2) mm0 = fmaxf(mm0, row[j]); j += 32;
            if (j < H2) mm1 = fmaxf(mm1, row[j]);
            float m = fmaxf(fmaxf(mm0, mm1), fmaxf(mm2, mm3));
#pragma unroll
            for (int o = 16; o; o >>= 1) m = fmaxf(m, __shfl_xor_sync(0xffffffffu, m, o));
            if (lane == 0) g_c[i] = m;
        }
        return;
    }
    if (w == 0) {
        float m = -3.4e38f;
        for (int j = lane; j < H2; j += 32) m = fmaxf(m, b2[j]);
#pragma unroll
        for (int o = 16; o; o >>= 1) m = fmaxf(m, __shfl_xor_sync(0xffffffffu, m, o));
        if (lane == 0) g_b2max = m;
    } else if (w == 1) {
        if (lane < ADIM) {
            float b = b3[lane];
            float vmax = (b > 0.0f) ? b : 0.5f * b;   // monotone v3 = b3*(1-2^-t)
            g_const[lane] = 0.05f * tanhf(vmax);
        }
    }
}

// ---------------- K1: fully fused kernel (12 warps) ----------------------
__global__ __launch_bounds__(NT, 2) void k_fused(const float* __restrict__ state,
                                                 const float* __restrict__ action,
                                                 const float* __restrict__ b1,
                                                 const float* __restrict__ W2,
                                                 const float* __restrict__ b2,
                                                 const float* __restrict__ W3,
                                                 const float* __restrict__ b3,
                                                 float* __restrict__ out) {
    extern __shared__ __align__(16) unsigned char sm[];
    __nv_bfloat16* sA  = reinterpret_cast<__nv_bfloat16*>(sm + SM_A);
    __nv_bfloat16* sB0 = reinterpret_cast<__nv_bfloat16*>(sm + SM_B0);
    __nv_bfloat16* sB1 = reinterpret_cast<__nv_bfloat16*>(sm + SM_B1);
    float*    stage   = reinterpret_cast<float*>(sm);           // epilogue overlay
    unsigned* stage_u = reinterpret_cast<unsigned*>(sm);
    float*    s_w2c   = reinterpret_cast<float*>(sm + SM_W2C);  // 22x300 W2 cache

    __shared__ float s_c[H1];
    __shared__ float s_b1[H1];
    __shared__ float s_const[ADIM];
    __shared__ float s_b2max;
    // spike compaction list
    __shared__ unsigned short s_spk[SPCAP];
    __shared__ int            s_nsp;
    // slow-path scratch
    __shared__ unsigned short s_fire[H1];
    __shared__ unsigned       s_msk[H1];
    __shared__ unsigned       s_mask2[H2];
    __shared__ unsigned short s_list2[TSTEPS][CAP2];
    __shared__ int            s_cnt2[TSTEPS];
    __shared__ unsigned short s_slow[32];
    __shared__ int            s_nslow, s_nf, s_any;

    const int tid  = threadIdx.x;
    const int lane = tid & 31;
    const int w    = tid >> 5;             // 0..11
    const int rg   = w / 6;                // 0..1
    const int cw   = w - rg * 6;           // 0..5
    const int nfr  = (cw < 4) ? 5 : 4;     // frags this warp owns
    const int fb   = (cw < 4) ? cw * 5 : 20 + (cw - 4) * 4;   // frag base
    const int m0   = blockIdx.x * 32;
    const unsigned lmask = (1u << lane) - 1u;

    if (tid == 0) { s_nslow = 0; s_nsp = 0; }

    auto load_B = [&](int c, __nv_bfloat16* dst) {
#pragma unroll
        for (int rep = 0; rep < 5; rep++) {
            int t2 = tid + rep * NT;
            if (t2 < 1792) {
                int r = t2 / 56, p = t2 - r * 56;
                cp16(dst + r * SBST + 8 * p,
                     &g_W1p[(size_t)(c * KCH + r) * NPAD + 8 * p]);
            }
        }
    };

    load_B(0, sB0);
    cp_commit();

    for (int i = tid; i < H1; i += NT) { s_c[i] = g_c[i]; s_b1[i] = b1[i]; }
    if (tid < ADIM) s_const[tid] = g_const[tid];
    if (tid == 32)  s_b2max = g_b2max;

    // A: load fp32 state/action, convert to bf16 smem (32 x 416, stride 424)
    for (int idx = tid; idx < 32 * SDIM; idx += NT) {
        int r = idx / SDIM, c = idx - r * SDIM;
        sA[r * SAST + c] = __float2bfloat16(state[(size_t)(m0 + r) * SDIM + c]);
    }
    for (int idx = tid; idx < 32 * ADIM; idx += NT) {
        int r = idx / ADIM, c = idx - r * ADIM;
        sA[r * SAST + SDIM + c] = __float2bfloat16(action[(size_t)(m0 + r) * ADIM + c]);
    }
    for (int idx = tid; idx < 32 * (DPAD - DIN); idx += NT) {
        int r = idx / (DPAD - DIN), c = idx - r * (DPAD - DIN);
        sA[r * SAST + DIN + c] = __float2bfloat16(0.0f);
    }

    wmma::fragment<wmma::accumulator, 16, 16, 16, float> acc[5];
#pragma unroll
    for (int f = 0; f < 5; f++) wmma::fill_fragment(acc[f], 0.0f);

    // ---- proven mainloop structure ----
    for (int c = 0; c < NCHK; c++) {
        __nv_bfloat16* cur = (c & 1) ? sB1 : sB0;
        __nv_bfloat16* nxt = (c & 1) ? sB0 : sB1;
        if (c + 1 < NCHK) {
            load_B(c + 1, nxt);
            cp_commit();
            cp_wait<1>();
        } else {
            cp_wait<0>();
        }
        __syncthreads();

#pragma unroll
        for (int ks = 0; ks < 2; ks++) {
            wmma::fragment<wmma::matrix_a, 16, 16, 16, __nv_bfloat16, wmma::row_major> afrag;
            wmma::load_matrix_sync(afrag,
                sA + (rg * 16) * SAST + c * KCH + ks * 16, SAST);
#pragma unroll
            for (int f = 0; f < 5; f++) {
                if (f < nfr) {
                    wmma::fragment<wmma::matrix_b, 16, 16, 16, __nv_bfloat16, wmma::row_major> bfrag;
                    wmma::load_matrix_sync(bfrag,
                        cur + (ks * 16) * SBST + (fb + f) * 16, SBST);
                    wmma::mma_sync(acc[f], afrag, bfrag, acc[f]);
                }
            }
        }
        __syncthreads();
    }

    // ---- epilogue: stage fp32 (overlay) ----
#pragma unroll
    for (int f = 0; f < 5; f++)
        if (f < nfr)
            wmma::store_matrix_sync(&stage[(rg * 16) * SBST + (fb + f) * 16],
                                    acc[f], SBST, wmma::mem_row_major);
    __syncthreads();

    // ---- LIF pass 1: zero non-spiking words, compact spiking candidates ----
    // 32*H1 = 12800 elements, 34 full-warp iterations (guarded).
    for (int it = 0; it < (32 * H1 + NT - 1) / NT; it++) {
        int idx = tid + it * NT;
        bool valid = idx < 32 * H1;
        int sidx = 0;
        float x = 0.0f;
        if (valid) {
            int r = idx / H1;
            int c = idx - r * H1;
            sidx = r * SBST + c;
            x = stage[sidx] + s_b1[c];
        }
        bool sp = valid && (x >= 0.999999f);   // v_t < x: x<1 can't spike
        unsigned bal = __ballot_sync(0xffffffffu, sp);
        if (bal) {
            int ldr = __ffs(bal) - 1;
            int base;
            if (lane == ldr) base = atomicAdd(&s_nsp, __popc(bal));
            base = __shfl_sync(0xffffffffu, base, ldr);
            if (sp) {
                int pos = base + __popc(bal & lmask);
                if (pos < SPCAP) {
                    s_spk[pos] = (unsigned short)sidx;   // sidx < 14592 fits
                } else {
                    // overflow fallback: compute inline (exact)
                    float v = 0.0f; unsigned word = 0u;
#pragma unroll
                    for (int t = 0; t < TSTEPS; t++) {
                        v = fmaf(x - v, 0.5f, v);
                        if (v >= 1.0f) { word |= (1u << t); v = 0.0f; }
                    }
                    stage_u[sidx] = word;
                }
            }
        }
        if (valid && !sp) stage_u[sidx] = 0u;
    }
    __syncthreads();

    // ---- LIF pass 2: dense 32-step simulation of compacted list ----
    {
        int nsp = s_nsp < SPCAP ? s_nsp : SPCAP;
        for (int i = tid; i < nsp; i += NT) {
            int sidx = s_spk[i];
            int r = sidx / SBST;
            int c = sidx - r * SBST;
            float x = stage[sidx] + s_b1[c];
            float v = 0.0f; unsigned word = 0u;
#pragma unroll
            for (int t = 0; t < TSTEPS; t++) {
                v = fmaf(x - v, 0.5f, v);
                if (v >= 1.0f) { word |= (1u << t); v = 0.0f; }
            }
            stage_u[sidx] = word;
        }
    }
    __syncthreads();

    // ---- per-row tight bound check: warp w handles rows w, w+12, w+24 ----
    for (int r = w; r < 32; r += 12) {
        int grow = m0 + r;
        float accu = 0.0f;                 // lane = timestep
        for (int ch = 0; ch < 13; ch++) {
            int i = ch * 32 + lane;
            unsigned word = (i < H1) ? stage_u[r * SBST + i] : 0u;
            unsigned bal = __ballot_sync(0xffffffffu, word != 0u);
            while (bal) {
                int b = __ffs(bal) - 1;
                bal &= bal - 1;
                unsigned wb = __shfl_sync(0xffffffffu, word, b);
                float ci = s_c[ch * 32 + b];
                if ((wb >> lane) & 1u) accu += ci;
            }
        }
        float u = s_b2max + accu;
        float vb = 0.0f, vbmax = -3.4e38f;
#pragma unroll
        for (int t = 0; t < TSTEPS; t++) {
            float ut = __shfl_sync(0xffffffffu, u, t);
            vb = 0.5f * (vb + ut);
            vbmax = fmaxf(vbmax, vb);
        }
        if (vbmax < 1.0f) {
            if (lane < ADIM) {
                float o = s_const[lane] + action[(size_t)grow * ADIM + lane];
                out[(size_t)grow * ADIM + lane] = fminf(fmaxf(o, -1.0f), 1.0f);
            }
        } else if (lane == 0) {
            int p = atomicAdd(&s_nslow, 1);
            s_slow[p] = (unsigned short)r;
        }
    }
    __syncthreads();

    // ---- in-CTA exact slow path: W2 prefetched in parallel chunks ----
    int nsl = s_nslow;
    for (int sr = 0; sr < nsl; sr++) {
        int r    = s_slow[sr];
        int grow = m0 + r;

        if (tid == 0) s_any = 0;
        if (w == 0) {
            int nf = 0;
            for (int ch = 0; ch < 13; ch++) {
                int i = ch * 32 + lane;
                unsigned m = (i < H1) ? stage_u[r * SBST + i] : 0u;
                unsigned bal = __ballot_sync(0xffffffffu, m != 0u);
                int pos = nf + __popc(bal & lmask);
                if (m != 0u) { s_fire[pos] = (unsigned short)i; s_msk[pos] = m; }
                nf += __popc(bal);
            }
            if (lane == 0) s_nf = nf;
        }
        __syncthreads();
        int nf = s_nf;

        // exact layer 2: single j-pass (384 >= 300); W2 via smem chunks
        float a0[TSTEPS];
#pragma unroll
        for (int t = 0; t < TSTEPS; t++) a0[t] = 0.0f;

        for (int base = 0; base < nf; base += W2C) {
            int n = nf - base; if (n > W2C) n = W2C;
            for (int idx = tid; idx < n * H2; idx += NT) {
                int q = idx / H2;
                int j = idx - q * H2;
                s_w2c[q * H2 + j] = W2[(size_t)s_fire[base + q] * H2 + j];
            }
            __syncthreads();
            if (tid < H2) {
                for (int q = 0; q < n; q++) {
                    float wv = s_w2c[q * H2 + tid];
                    unsigned m = s_msk[base + q];
#pragma unroll
                    for (int t = 0; t < TSTEPS; t++)
                        if ((m >> t) & 1u) a0[t] += wv;
                }
            }
            __syncthreads();
        }

        if (tid < H2) {
            float b2j = b2[tid];
            float v2 = 0.0f;
            unsigned mask2 = 0u;
#pragma unroll
            for (int t = 0; t < TSTEPS; t++) {
                float x2 = b2j + a0[t];
                v2 += (x2 - v2) * 0.5f;
                if (v2 >= 1.0f) { mask2 |= (1u << t); v2 = 0.0f; }
            }
            s_mask2[tid] = mask2;
            if (mask2) atomicOr(&s_any, 1);
        }
        __syncthreads();

        if (s_any == 0) {
            if (tid < ADIM) {
                float o = s_const[tid] + action[(size_t)grow * ADIM + tid];
                out[(size_t)grow * ADIM + tid] = fminf(fmaxf(o, -1.0f), 1.0f);
            }
        } else {
            for (int t = w; t < TSTEPS; t += 12) {
                int cnt = 0;
                for (int ch = 0; ch * 32 < H2; ch++) {
                    int j = ch * 32 + lane;
                    int pred = 0;
                    if (j < H2) pred = (int)((s_mask2[j] >> t) & 1u);
                    unsigned bal = __ballot_sync(0xffffffffu, pred);
                    int pos = cnt + __popc(bal & lmask);
                    if (pred && pos < CAP2) s_list2[t][pos] = (unsigned short)j;
                    cnt += __popc(bal);
                }
                s_cnt2[t] = cnt < CAP2 ? cnt : CAP2;
            }
            __syncthreads();
            if (tid < ADIM) {
                int k = tid;
                float b3k = b3[k];
                float v3 = 0.0f, vmax = -3.4e38f;
                for (int t = 0; t < TSTEPS; t++) {
                    float x3 = b3k;
                    int n = s_cnt2[t];
                    for (int q = 0; q < n; q++)
                        x3 += W3[s_list2[t][q] * ADIM + k];
                    v3 += (x3 - v3) * 0.5f;
                    vmax = fmaxf(vmax, v3);
                }
                float a2 = 0.05f * tanhf(vmax);
                float o = a2 + action[(size_t)grow * ADIM + k];
                out[(size_t)grow * ADIM + k] = fminf(fmaxf(o, -1.0f), 1.0f);
            }
        }
        __syncthreads();
    }
}

// ---------------- launch ----------------
extern "C" void kernel_launch(void* const* d_in, const int* in_sizes, int n_in,
                              void* d_out, int out_size) {
    (void)in_sizes; (void)n_in; (void)out_size;
    const float* state  = (const float*)d_in[0];
    const float* action = (const float*)d_in[1];
    const float* W1     = (const float*)d_in[2];
    const float* b1     = (const float*)d_in[3];
    const float* W2     = (const float*)d_in[4];
    const float* b2     = (const float*)d_in[5];
    const float* W3     = (const float*)d_in[6];
    const float* b3     = (const float*)d_in[7];
    float* out = (float*)d_out;

    cudaFuncSetAttribute(k_fused, cudaFuncAttributeMaxDynamicSharedMemorySize,
                         SM_DYN);

    k_setup<<<PACKB + CBLK + 1, 256>>>(W1, W2, b2, b3);

    k_fused<<<BATCH / 32, NT, SM_DYN>>>(state, action, b1, W2, b2, W3, b3, out);
}

// round 15
// speedup vs baseline: 1.7390x; 1.0011x over previous
#include <cuda_runtime.h>
#include <cuda_bf16.h>
#include <mma.h>
#include <math.h>

using namespace nvcuda;

#define BATCH 8192
#define SDIM  376
#define ADIM  17
#define DIN   393
#define DPAD  416           // padded K: 13 chunks of 32
#define KCH   32
#define NCHK  13
#define H1    400
#define NPAD  448           // padded N
#define SBST  456           // B smem stride (odd multiple of 8 -> conflict-free)
#define SAST  424           // full-K A smem stride
#define H2    300
#define TSTEPS 32
#define CAP2  96
#define W2C   22            // W2 rows cached per chunk in the in-CTA slow path
#define NT    384           // threads per CTA (12 warps)
#define SPCAP 2048          // spike-candidate list capacity (exp ~512)

// smem layout (dynamic): [A 32*424*2 = 27136][B0 29184][B1 29184] = 85504
// epilogue overlay: fp32 stage [0, 58368) ; W2 cache [58368, 85504)
#define SM_A     0
#define SM_B0    27136
#define SM_B1    (27136 + 29184)
#define SM_DYN   (27136 + 2 * 29184)
#define SM_STAGE_BYTES (32 * SBST * 4)     // 58368
#define SM_W2C   SM_STAGE_BYTES

// setup-kernel grid split
#define PACKB   ((DPAD * NPAD) / 1024)     // 182 blocks pack W1 (4 elems/thread)
#define CBLK    ((H1 + 7) / 8)             // 50 blocks compute c_i (warp/row)

// ---------------- static device scratch ----------------
__device__ __align__(16) __nv_bfloat16 g_W1p[(size_t)DPAD * NPAD];
__device__ float g_c[H1];          // c_i = max_j W2[i,j]
__device__ float g_b2max;
__device__ float g_const[ADIM];    // 0.05*tanh(vmax(b3_k))

// ---------------- cp.async helpers ----------------
__device__ __forceinline__ void cp16(void* dst, const void* src) {
    unsigned d = (unsigned)__cvta_generic_to_shared(dst);
    asm volatile("cp.async.cg.shared.global [%0], [%1], 16;\n" :: "r"(d), "l"(src));
}
__device__ __forceinline__ void cp_commit() {
    asm volatile("cp.async.commit_group;\n");
}
template<int N> __device__ __forceinline__ void cp_wait() {
    asm volatile("cp.async.wait_group %0;\n" :: "n"(N));
}

// ---------------- K_setup: pack W1 + constants (one launch) ----------------
__global__ __launch_bounds__(256) void k_setup(const float* __restrict__ W1,
                                               const float* __restrict__ W2,
                                               const float* __restrict__ b2,
                                               const float* __restrict__ b3) {
    int bid = blockIdx.x;
    int tid = threadIdx.x;
    if (bid < PACKB) {
        int e0 = (bid * 256 + tid) * 4;
        int r = e0 / NPAD;
        int c = e0 - r * NPAD;
        __nv_bfloat16 v[4];
        if (r < DIN && c < H1) {
            float4 f = *reinterpret_cast<const float4*>(&W1[(size_t)r * H1 + c]);
            v[0] = __float2bfloat16(f.x); v[1] = __float2bfloat16(f.y);
            v[2] = __float2bfloat16(f.z); v[3] = __float2bfloat16(f.w);
        } else {
            v[0] = v[1] = v[2] = v[3] = __float2bfloat16(0.0f);
        }
        *reinterpret_cast<uint2*>(&g_W1p[e0]) = *reinterpret_cast<uint2*>(v);
        return;
    }
    int lane = tid & 31;
    int w    = tid >> 5;
    if (bid < PACKB + CBLK) {
        int i = (bid - PACKB) * 8 + w;     // one warp per neuron row
        if (i < H1) {
            float mm0 = -3.4e38f, mm1 = -3.4e38f, mm2 = -3.4e38f, mm3 = -3.4e38f;
            const float* row = &W2[(size_t)i * H2];
            int j = lane;
#pragma unroll
            for (int k = 0; k < 2; k++) {
                if (j < H2) mm0 = fmaxf(mm0, row[j]); j += 32;
                if (j < H2) mm1 = fmaxf(mm1, row[j]); j += 32;
                if (j < H2) mm2 = fmaxf(mm2, row[j]); j += 32;
                if (j < H2) mm3 = fmaxf(mm3, row[j]); j += 32;
            }
            if (j < H2) mm0 = fmaxf(mm0, row[j]); j += 32;
            if (j < H2) mm1 = fmaxf(mm1, row[j]);
            float m = fmaxf(fmaxf(mm0, mm1), fmaxf(mm2, mm3));
#pragma unroll
            for (int o = 16; o; o >>= 1) m = fmaxf(m, __shfl_xor_sync(0xffffffffu, m, o));
            if (lane == 0) g_c[i] = m;
        }
        return;
    }
    if (w == 0) {
        float m = -3.4e38f;
        for (int j = lane; j < H2; j += 32) m = fmaxf(m, b2[j]);
#pragma unroll
        for (int o = 16; o; o >>= 1) m = fmaxf(m, __shfl_xor_sync(0xffffffffu, m, o));
        if (lane == 0) g_b2max = m;
    } else if (w == 1) {
        if (lane < ADIM) {
            float b = b3[lane];
            float vmax = (b > 0.0f) ? b : 0.5f * b;   // monotone v3 = b3*(1-2^-t)
            g_const[lane] = 0.05f * tanhf(vmax);
        }
    }
}

// ---------------- K1: fully fused kernel (12 warps) ----------------------
__global__ __launch_bounds__(NT, 2) void k_fused(const float* __restrict__ state,
                                                 const float* __restrict__ action,
                                                 const float* __restrict__ b1,
                                                 const float* __restrict__ W2,
                                                 const float* __restrict__ b2,
                                                 const float* __restrict__ W3,
                                                 const float* __restrict__ b3,
                                                 float* __restrict__ out) {
    extern __shared__ __align__(16) unsigned char sm[];
    __nv_bfloat16* sA  = reinterpret_cast<__nv_bfloat16*>(sm + SM_A);
    __nv_bfloat16* sB0 = reinterpret_cast<__nv_bfloat16*>(sm + SM_B0);
    __nv_bfloat16* sB1 = reinterpret_cast<__nv_bfloat16*>(sm + SM_B1);
    float*    stage   = reinterpret_cast<float*>(sm);           // epilogue overlay
    unsigned* stage_u = reinterpret_cast<unsigned*>(sm);
    float*    s_w2c   = reinterpret_cast<float*>(sm + SM_W2C);  // 22x300 W2 cache

    __shared__ float s_c[H1];
    __shared__ float s_b1[H1];
    __shared__ float s_const[ADIM];
    __shared__ float s_b2max;
    // spike compaction list
    __shared__ unsigned short s_spk[SPCAP];
    __shared__ int            s_nsp;
    // slow-path scratch
    __shared__ unsigned short s_fire[H1];
    __shared__ unsigned       s_msk[H1];
    __shared__ unsigned       s_mask2[H2];
    __shared__ unsigned short s_list2[TSTEPS][CAP2];
    __shared__ int            s_cnt2[TSTEPS];
    __shared__ unsigned short s_slow[32];
    __shared__ int            s_nslow, s_nf, s_any;

    const int tid  = threadIdx.x;
    const int lane = tid & 31;
    const int w    = tid >> 5;             // 0..11
    const int rg   = w / 6;                // 0..1
    const int cw   = w - rg * 6;           // 0..5
    const int nfr  = (cw < 4) ? 5 : 4;     // frags this warp owns
    const int fb   = (cw < 4) ? cw * 5 : 20 + (cw - 4) * 4;   // frag base
    const int m0   = blockIdx.x * 32;
    const unsigned lmask = (1u << lane) - 1u;

    if (tid == 0) { s_nslow = 0; s_nsp = 0; }

    auto load_B = [&](int c, __nv_bfloat16* dst) {
#pragma unroll
        for (int rep = 0; rep < 5; rep++) {
            int t2 = tid + rep * NT;
            if (t2 < 1792) {
                int r = t2 / 56, p = t2 - r * 56;
                cp16(dst + r * SBST + 8 * p,
                     &g_W1p[(size_t)(c * KCH + r) * NPAD + 8 * p]);
            }
        }
    };

    load_B(0, sB0);
    cp_commit();

    for (int i = tid; i < H1; i += NT) { s_c[i] = g_c[i]; s_b1[i] = b1[i]; }
    if (tid < ADIM) s_const[tid] = g_const[tid];
    if (tid == 32)  s_b2max = g_b2max;

    // A: load fp32 state/action, convert to bf16 smem (32 x 416, stride 424)
    for (int idx = tid; idx < 32 * SDIM; idx += NT) {
        int r = idx / SDIM, c = idx - r * SDIM;
        sA[r * SAST + c] = __float2bfloat16(state[(size_t)(m0 + r) * SDIM + c]);
    }
    for (int idx = tid; idx < 32 * ADIM; idx += NT) {
        int r = idx / ADIM, c = idx - r * ADIM;
        sA[r * SAST + SDIM + c] = __float2bfloat16(action[(size_t)(m0 + r) * ADIM + c]);
    }
    for (int idx = tid; idx < 32 * (DPAD - DIN); idx += NT) {
        int r = idx / (DPAD - DIN), c = idx - r * (DPAD - DIN);
        sA[r * SAST + DIN + c] = __float2bfloat16(0.0f);
    }

    wmma::fragment<wmma::accumulator, 16, 16, 16, float> acc[5];
#pragma unroll
    for (int f = 0; f < 5; f++) wmma::fill_fragment(acc[f], 0.0f);

    // ---- single-sync mainloop (clean: no offset arrays) ----
    // iter c: wait for chunk c, barrier (also retires mma(c-1) on nxt buffer),
    // issue load(c+1) into nxt, then mma on cur.
    for (int c = 0; c < NCHK; c++) {
        __nv_bfloat16* cur = (c & 1) ? sB1 : sB0;
        __nv_bfloat16* nxt = (c & 1) ? sB0 : sB1;
        cp_wait<0>();
        __syncthreads();
        if (c + 1 < NCHK) {
            load_B(c + 1, nxt);
            cp_commit();
        }
#pragma unroll
        for (int ks = 0; ks < 2; ks++) {
            wmma::fragment<wmma::matrix_a, 16, 16, 16, __nv_bfloat16, wmma::row_major> afrag;
            wmma::load_matrix_sync(afrag,
                sA + (rg * 16) * SAST + c * KCH + ks * 16, SAST);
#pragma unroll
            for (int f = 0; f < 5; f++) {
                if (f < nfr) {
                    wmma::fragment<wmma::matrix_b, 16, 16, 16, __nv_bfloat16, wmma::row_major> bfrag;
                    wmma::load_matrix_sync(bfrag,
                        cur + (ks * 16) * SBST + (fb + f) * 16, SBST);
                    wmma::mma_sync(acc[f], afrag, bfrag, acc[f]);
                }
            }
        }
    }
    __syncthreads();                 // all mma done before stage overlay

    // ---- epilogue: stage fp32 (overlay) ----
#pragma unroll
    for (int f = 0; f < 5; f++)
        if (f < nfr)
            wmma::store_matrix_sync(&stage[(rg * 16) * SBST + (fb + f) * 16],
                                    acc[f], SBST, wmma::mem_row_major);
    __syncthreads();

    // ---- LIF pass 1: zero non-spiking words, compact spiking candidates ----
    for (int it = 0; it < (32 * H1 + NT - 1) / NT; it++) {
        int idx = tid + it * NT;
        bool valid = idx < 32 * H1;
        int sidx = 0;
        float x = 0.0f;
        if (valid) {
            int r = idx / H1;
            int c = idx - r * H1;
            sidx = r * SBST + c;
            x = stage[sidx] + s_b1[c];
        }
        bool sp = valid && (x >= 0.999999f);   // v_t < x: x<1 can't spike
        unsigned bal = __ballot_sync(0xffffffffu, sp);
        if (bal) {
            int ldr = __ffs(bal) - 1;
            int base;
            if (lane == ldr) base = atomicAdd(&s_nsp, __popc(bal));
            base = __shfl_sync(0xffffffffu, base, ldr);
            if (sp) {
                int pos = base + __popc(bal & lmask);
                if (pos < SPCAP) {
                    s_spk[pos] = (unsigned short)sidx;   // sidx < 14592 fits
                } else {
                    float v = 0.0f; unsigned word = 0u;
#pragma unroll
                    for (int t = 0; t < TSTEPS; t++) {
                        v = fmaf(x - v, 0.5f, v);
                        if (v >= 1.0f) { word |= (1u << t); v = 0.0f; }
                    }
                    stage_u[sidx] = word;
                }
            }
        }
        if (valid && !sp) stage_u[sidx] = 0u;
    }
    __syncthreads();

    // ---- LIF pass 2: dense 32-step simulation of compacted list ----
    {
        int nsp = s_nsp < SPCAP ? s_nsp : SPCAP;
        for (int i = tid; i < nsp; i += NT) {
            int sidx = s_spk[i];
            int r = sidx / SBST;
            int c = sidx - r * SBST;
            float x = stage[sidx] + s_b1[c];
            float v = 0.0f; unsigned word = 0u;
#pragma unroll
            for (int t = 0; t < TSTEPS; t++) {
                v = fmaf(x - v, 0.5f, v);
                if (v >= 1.0f) { word |= (1u << t); v = 0.0f; }
            }
            stage_u[sidx] = word;
        }
    }
    __syncthreads();

    // ---- per-row tight bound check: warp w handles rows w, w+12, w+24 ----
    for (int r = w; r < 32; r += 12) {
        int grow = m0 + r;
        float accu = 0.0f;                 // lane = timestep
        for (int ch = 0; ch < 13; ch++) {
            int i = ch * 32 + lane;
            unsigned word = (i < H1) ? stage_u[r * SBST + i] : 0u;
            unsigned bal = __ballot_sync(0xffffffffu, word != 0u);
            while (bal) {
                int b = __ffs(bal) - 1;
                bal &= bal - 1;
                unsigned wb = __shfl_sync(0xffffffffu, word, b);
                float ci = s_c[ch * 32 + b];
                if ((wb >> lane) & 1u) accu += ci;
            }
        }
        float u = s_b2max + accu;
        float vb = 0.0f, vbmax = -3.4e38f;
#pragma unroll
        for (int t = 0; t < TSTEPS; t++) {
            float ut = __shfl_sync(0xffffffffu, u, t);
            vb = 0.5f * (vb + ut);
            vbmax = fmaxf(vbmax, vb);
        }
        if (vbmax < 1.0f) {
            if (lane < ADIM) {
                float o = s_const[lane] + action[(size_t)grow * ADIM + lane];
                out[(size_t)grow * ADIM + lane] = fminf(fmaxf(o, -1.0f), 1.0f);
            }
        } else if (lane == 0) {
            int p = atomicAdd(&s_nslow, 1);
            s_slow[p] = (unsigned short)r;
        }
    }
    __syncthreads();

    // ---- in-CTA exact slow path: W2 prefetched in parallel chunks ----
    int nsl = s_nslow;
    for (int sr = 0; sr < nsl; sr++) {
        int r    = s_slow[sr];
        int grow = m0 + r;

        if (tid == 0) s_any = 0;
        if (w == 0) {
            int nf = 0;
            for (int ch = 0; ch < 13; ch++) {
                int i = ch * 32 + lane;
                unsigned m = (i < H1) ? stage_u[r * SBST + i] : 0u;
                unsigned bal = __ballot_sync(0xffffffffu, m != 0u);
                int pos = nf + __popc(bal & lmask);
                if (m != 0u) { s_fire[pos] = (unsigned short)i; s_msk[pos] = m; }
                nf += __popc(bal);
            }
            if (lane == 0) s_nf = nf;
        }
        __syncthreads();
        int nf = s_nf;

        float a0[TSTEPS];
#pragma unroll
        for (int t = 0; t < TSTEPS; t++) a0[t] = 0.0f;

        for (int base = 0; base < nf; base += W2C) {
            int n = nf - base; if (n > W2C) n = W2C;
            for (int idx = tid; idx < n * H2; idx += NT) {
                int q = idx / H2;
                int j = idx - q * H2;
                s_w2c[q * H2 + j] = W2[(size_t)s_fire[base + q] * H2 + j];
            }
            __syncthreads();
            if (tid < H2) {
                for (int q = 0; q < n; q++) {
                    float wv = s_w2c[q * H2 + tid];
                    unsigned m = s_msk[base + q];
#pragma unroll
                    for (int t = 0; t < TSTEPS; t++)
                        if ((m >> t) & 1u) a0[t] += wv;
                }
            }
            __syncthreads();
        }

        if (tid < H2) {
            float b2j = b2[tid];
            float v2 = 0.0f;
            unsigned mask2 = 0u;
#pragma unroll
            for (int t = 0; t < TSTEPS; t++) {
                float x2 = b2j + a0[t];
                v2 += (x2 - v2) * 0.5f;
                if (v2 >= 1.0f) { mask2 |= (1u << t); v2 = 0.0f; }
            }
            s_mask2[tid] = mask2;
            if (mask2) atomicOr(&s_any, 1);
        }
        __syncthreads();

        if (s_any == 0) {
            if (tid < ADIM) {
                float o = s_const[tid] + action[(size_t)grow * ADIM + tid];
                out[(size_t)grow * ADIM + tid] = fminf(fmaxf(o, -1.0f), 1.0f);
            }
        } else {
            for (int t = w; t < TSTEPS; t += 12) {
                int cnt = 0;
                for (int ch = 0; ch * 32 < H2; ch++) {
                    int j = ch * 32 + lane;
                    int pred = 0;
                    if (j < H2) pred = (int)((s_mask2[j] >> t) & 1u);
                    unsigned bal = __ballot_sync(0xffffffffu, pred);
                    int pos = cnt + __popc(bal & lmask);
                    if (pred && pos < CAP2) s_list2[t][pos] = (unsigned short)j;
                    cnt += __popc(bal);
                }
                s_cnt2[t] = cnt < CAP2 ? cnt : CAP2;
            }
            __syncthreads();
            if (tid < ADIM) {
                int k = tid;
                float b3k = b3[k];
                float v3 = 0.0f, vmax = -3.4e38f;
                for (int t = 0; t < TSTEPS; t++) {
                    float x3 = b3k;
                    int n = s_cnt2[t];
                    for (int q = 0; q < n; q++)
                        x3 += W3[s_list2[t][q] * ADIM + k];
                    v3 += (x3 - v3) * 0.5f;
                    vmax = fmaxf(vmax, v3);
                }
                float a2 = 0.05f * tanhf(vmax);
                float o = a2 + action[(size_t)grow * ADIM + k];
                out[(size_t)grow * ADIM + k] = fminf(fmaxf(o, -1.0f), 1.0f);
            }
        }
        __syncthreads();
    }
}

// ---------------- launch ----------------
extern "C" void kernel_launch(void* const* d_in, const int* in_sizes, int n_in,
                              void* d_out, int out_size) {
    (void)in_sizes; (void)n_in; (void)out_size;
    const float* state  = (const float*)d_in[0];
    const float* action = (const float*)d_in[1];
    const float* W1     = (const float*)d_in[2];
    const float* b1     = (const float*)d_in[3];
    const float* W2     = (const float*)d_in[4];
    const float* b2     = (const float*)d_in[5];
    const float* W3     = (const float*)d_in[6];
    const float* b3     = (const float*)d_in[7];
    float* out = (float*)d_out;

    cudaFuncSetAttribute(k_fused, cudaFuncAttributeMaxDynamicSharedMemorySize,
                         SM_DYN);

    k_setup<<<PACKB + CBLK + 1, 256>>>(W1, W2, b2, b3);

    k_fused<<<BATCH / 32, NT, SM_DYN>>>(state, action, b1, W2, b2, W3, b3, out);
}

// round 16
// speedup vs baseline: 1.8292x; 1.0519x over previous
#include <cuda_runtime.h>
#include <cuda_bf16.h>
#include <mma.h>
#include <math.h>

using namespace nvcuda;

#define BATCH 8192
#define SDIM  376
#define ADIM  17
#define DIN   393
#define DPAD  416           // padded K: 13 chunks of 32
#define KCH   32
#define NCHK  13
#define H1    400
#define NPAD  448           // padded N
#define SBST  456           // B smem stride (odd multiple of 8 -> conflict-free)
#define SAST  424           // full-K A smem stride
#define H2    300
#define TSTEPS 32
#define CAP2  96
#define W2C   22            // W2 rows cached per chunk in the in-CTA slow path
#define NT    512           // threads per CTA (16 warps)
#define SPCAP 2048          // spike-candidate list capacity (exp ~512)

// smem layout (dynamic): [A 32*424*2 = 27136][B0 29184][B1 29184] = 85504
// epilogue overlay: fp32 stage [0, 58368) ; W2 cache [58368, 85504)
#define SM_A     0
#define SM_B0    27136
#define SM_B1    (27136 + 29184)
#define SM_DYN   (27136 + 2 * 29184)
#define SM_STAGE_BYTES (32 * SBST * 4)     // 58368
#define SM_W2C   SM_STAGE_BYTES

// setup-kernel grid split
#define PACKB   ((DPAD * NPAD) / 1024)     // 182 blocks pack W1 (4 elems/thread)
#define CBLK    ((H1 + 7) / 8)             // 50 blocks compute c_i (warp/row)

// ---------------- static device scratch ----------------
__device__ __align__(16) __nv_bfloat16 g_W1p[(size_t)DPAD * NPAD];
__device__ float g_c[H1];          // c_i = max_j W2[i,j]
__device__ float g_b2max;
__device__ float g_const[ADIM];    // 0.05*tanh(vmax(b3_k))

// ---------------- cp.async helpers ----------------
__device__ __forceinline__ void cp16(void* dst, const void* src) {
    unsigned d = (unsigned)__cvta_generic_to_shared(dst);
    asm volatile("cp.async.cg.shared.global [%0], [%1], 16;\n" :: "r"(d), "l"(src));
}
__device__ __forceinline__ void cp_commit() {
    asm volatile("cp.async.commit_group;\n");
}
template<int N> __device__ __forceinline__ void cp_wait() {
    asm volatile("cp.async.wait_group %0;\n" :: "n"(N));
}

// ---------------- K_setup: pack W1 + constants (one launch) ----------------
__global__ __launch_bounds__(256) void k_setup(const float* __restrict__ W1,
                                               const float* __restrict__ W2,
                                               const float* __restrict__ b2,
                                               const float* __restrict__ b3) {
    int bid = blockIdx.x;
    int tid = threadIdx.x;
    if (bid < PACKB) {
        int e0 = (bid * 256 + tid) * 4;
        int r = e0 / NPAD;
        int c = e0 - r * NPAD;
        __nv_bfloat16 v[4];
        if (r < DIN && c < H1) {
            float4 f = *reinterpret_cast<const float4*>(&W1[(size_t)r * H1 + c]);
            v[0] = __float2bfloat16(f.x); v[1] = __float2bfloat16(f.y);
            v[2] = __float2bfloat16(f.z); v[3] = __float2bfloat16(f.w);
        } else {
            v[0] = v[1] = v[2] = v[3] = __float2bfloat16(0.0f);
        }
        *reinterpret_cast<uint2*>(&g_W1p[e0]) = *reinterpret_cast<uint2*>(v);
        return;
    }
    int lane = tid & 31;
    int w    = tid >> 5;
    if (bid < PACKB + CBLK) {
        int i = (bid - PACKB) * 8 + w;     // one warp per neuron row
        if (i < H1) {
            float mm0 = -3.4e38f, mm1 = -3.4e38f, mm2 = -3.4e38f, mm3 = -3.4e38f;
            const float* row = &W2[(size_t)i * H2];
            int j = lane;
#pragma unroll
            for (int k = 0; k < 2; k++) {
                if (j < H2) mm0 = fmaxf(mm0, row[j]); j += 32;
                if (j < H2) mm1 = fmaxf(mm1, row[j]); j += 32;
                if (j < H2) mm2 = fmaxf(mm2, row[j]); j += 32;
                if (j < H2) mm3 = fmaxf(mm3, row[j]); j += 32;
            }
            if (j < H2) mm0 = fmaxf(mm0, row[j]); j += 32;
            if (j < H2) mm1 = fmaxf(mm1, row[j]);
            float m = fmaxf(fmaxf(mm0, mm1), fmaxf(mm2, mm3));
#pragma unroll
            for (int o = 16; o; o >>= 1) m = fmaxf(m, __shfl_xor_sync(0xffffffffu, m, o));
            if (lane == 0) g_c[i] = m;
        }
        return;
    }
    if (w == 0) {
        float m = -3.4e38f;
        for (int j = lane; j < H2; j += 32) m = fmaxf(m, b2[j]);
#pragma unroll
        for (int o = 16; o; o >>= 1) m = fmaxf(m, __shfl_xor_sync(0xffffffffu, m, o));
        if (lane == 0) g_b2max = m;
    } else if (w == 1) {
        if (lane < ADIM) {
            float b = b3[lane];
            float vmax = (b > 0.0f) ? b : 0.5f * b;   // monotone v3 = b3*(1-2^-t)
            g_const[lane] = 0.05f * tanhf(vmax);
        }
    }
}

// ---------------- K1: fully fused kernel (16 warps) ----------------------
// warp w: rowgroup rg = w>>3 (16 rows), colset cw = w&7 with widths
// {4,4,4,4,3,3,3,3} frags of 16 cols => 448 cols total per rowgroup.
__global__ __launch_bounds__(NT, 2) void k_fused(const float* __restrict__ state,
                                                 const float* __restrict__ action,
                                                 const float* __restrict__ b1,
                                                 const float* __restrict__ W2,
                                                 const float* __restrict__ b2,
                                                 const float* __restrict__ W3,
                                                 const float* __restrict__ b3,
                                                 float* __restrict__ out) {
    extern __shared__ __align__(16) unsigned char sm[];
    __nv_bfloat16* sA  = reinterpret_cast<__nv_bfloat16*>(sm + SM_A);
    __nv_bfloat16* sB0 = reinterpret_cast<__nv_bfloat16*>(sm + SM_B0);
    __nv_bfloat16* sB1 = reinterpret_cast<__nv_bfloat16*>(sm + SM_B1);
    float*    stage   = reinterpret_cast<float*>(sm);           // epilogue overlay
    unsigned* stage_u = reinterpret_cast<unsigned*>(sm);
    float*    s_w2c   = reinterpret_cast<float*>(sm + SM_W2C);  // 22x300 W2 cache

    __shared__ float s_c[H1];
    __shared__ float s_b1[H1];
    __shared__ float s_const[ADIM];
    __shared__ float s_b2max;
    // spike compaction list
    __shared__ unsigned short s_spk[SPCAP];
    __shared__ int            s_nsp;
    // slow-path scratch
    __shared__ unsigned short s_fire[H1];
    __shared__ unsigned       s_msk[H1];
    __shared__ unsigned       s_mask2[H2];
    __shared__ unsigned short s_list2[TSTEPS][CAP2];
    __shared__ int            s_cnt2[TSTEPS];
    __shared__ unsigned short s_slow[32];
    __shared__ int            s_nslow, s_nf, s_any;

    const int tid  = threadIdx.x;
    const int lane = tid & 31;
    const int w    = tid >> 5;             // 0..15
    const int rg   = w >> 3;               // 0..1
    const int cw   = w & 7;                // 0..7
    const int nfr  = (cw < 4) ? 4 : 3;     // frags this warp owns
    const int fb   = (cw < 4) ? cw * 4 : 16 + (cw - 4) * 3;   // frag base
    const int m0   = blockIdx.x * 32;
    const unsigned lmask = (1u << lane) - 1u;

    if (tid == 0) { s_nslow = 0; s_nsp = 0; }

    auto load_B = [&](int c, __nv_bfloat16* dst) {
        // 32 k-rows x 448 cols -> 1792 cp16 (4 reps, guarded)
#pragma unroll
        for (int rep = 0; rep < 4; rep++) {
            int t2 = tid + rep * NT;
            if (t2 < 1792) {
                int r = t2 / 56, p = t2 - r * 56;
                cp16(dst + r * SBST + 8 * p,
                     &g_W1p[(size_t)(c * KCH + r) * NPAD + 8 * p]);
            }
        }
    };

    load_B(0, sB0);
    cp_commit();

    for (int i = tid; i < H1; i += NT) { s_c[i] = g_c[i]; s_b1[i] = b1[i]; }
    if (tid < ADIM) s_const[tid] = g_const[tid];
    if (tid == 32)  s_b2max = g_b2max;

    // A: load fp32 state/action, convert to bf16 smem (32 x 416, stride 424)
    for (int idx = tid; idx < 32 * SDIM; idx += NT) {
        int r = idx / SDIM, c = idx - r * SDIM;
        sA[r * SAST + c] = __float2bfloat16(state[(size_t)(m0 + r) * SDIM + c]);
    }
    for (int idx = tid; idx < 32 * ADIM; idx += NT) {
        int r = idx / ADIM, c = idx - r * ADIM;
        sA[r * SAST + SDIM + c] = __float2bfloat16(action[(size_t)(m0 + r) * ADIM + c]);
    }
    for (int idx = tid; idx < 32 * (DPAD - DIN); idx += NT) {
        int r = idx / (DPAD - DIN), c = idx - r * (DPAD - DIN);
        sA[r * SAST + DIN + c] = __float2bfloat16(0.0f);
    }

    wmma::fragment<wmma::accumulator, 16, 16, 16, float> acc[4];
#pragma unroll
    for (int f = 0; f < 4; f++) wmma::fill_fragment(acc[f], 0.0f);

    // ---- single-sync mainloop ----
    for (int c = 0; c < NCHK; c++) {
        __nv_bfloat16* cur = (c & 1) ? sB1 : sB0;
        __nv_bfloat16* nxt = (c & 1) ? sB0 : sB1;
        cp_wait<0>();
        __syncthreads();
        if (c + 1 < NCHK) {
            load_B(c + 1, nxt);
            cp_commit();
        }
#pragma unroll
        for (int ks = 0; ks < 2; ks++) {
            wmma::fragment<wmma::matrix_a, 16, 16, 16, __nv_bfloat16, wmma::row_major> afrag;
            wmma::load_matrix_sync(afrag,
                sA + (rg * 16) * SAST + c * KCH + ks * 16, SAST);
#pragma unroll
            for (int f = 0; f < 4; f++) {
                if (f < nfr) {
                    wmma::fragment<wmma::matrix_b, 16, 16, 16, __nv_bfloat16, wmma::row_major> bfrag;
                    wmma::load_matrix_sync(bfrag,
                        cur + (ks * 16) * SBST + (fb + f) * 16, SBST);
                    wmma::mma_sync(acc[f], afrag, bfrag, acc[f]);
                }
            }
        }
    }
    __syncthreads();                 // all mma done before stage overlay

    // ---- epilogue: stage fp32 (overlay) ----
#pragma unroll
    for (int f = 0; f < 4; f++)
        if (f < nfr)
            wmma::store_matrix_sync(&stage[(rg * 16) * SBST + (fb + f) * 16],
                                    acc[f], SBST, wmma::mem_row_major);
    __syncthreads();

    // ---- LIF pass 1: zero non-spiking words, compact spiking candidates ----
    for (int it = 0; it < (32 * H1 + NT - 1) / NT; it++) {
        int idx = tid + it * NT;
        bool valid = idx < 32 * H1;
        int sidx = 0;
        float x = 0.0f;
        if (valid) {
            int r = idx / H1;
            int c = idx - r * H1;
            sidx = r * SBST + c;
            x = stage[sidx] + s_b1[c];
        }
        bool sp = valid && (x >= 0.999999f);   // v_t < x: x<1 can't spike
        unsigned bal = __ballot_sync(0xffffffffu, sp);
        if (bal) {
            int ldr = __ffs(bal) - 1;
            int base;
            if (lane == ldr) base = atomicAdd(&s_nsp, __popc(bal));
            base = __shfl_sync(0xffffffffu, base, ldr);
            if (sp) {
                int pos = base + __popc(bal & lmask);
                if (pos < SPCAP) {
                    s_spk[pos] = (unsigned short)sidx;   // sidx < 14592 fits
                } else {
                    float v = 0.0f; unsigned word = 0u;
#pragma unroll
                    for (int t = 0; t < TSTEPS; t++) {
                        v = fmaf(x - v, 0.5f, v);
                        if (v >= 1.0f) { word |= (1u << t); v = 0.0f; }
                    }
                    stage_u[sidx] = word;
                }
            }
        }
        if (valid && !sp) stage_u[sidx] = 0u;
    }
    __syncthreads();

    // ---- LIF pass 2: dense 32-step simulation of compacted list ----
    {
        int nsp = s_nsp < SPCAP ? s_nsp : SPCAP;
        for (int i = tid; i < nsp; i += NT) {
            int sidx = s_spk[i];
            int r = sidx / SBST;
            int c = sidx - r * SBST;
            float x = stage[sidx] + s_b1[c];
            float v = 0.0f; unsigned word = 0u;
#pragma unroll
            for (int t = 0; t < TSTEPS; t++) {
                v = fmaf(x - v, 0.5f, v);
                if (v >= 1.0f) { word |= (1u << t); v = 0.0f; }
            }
            stage_u[sidx] = word;
        }
    }
    __syncthreads();

    // ---- per-row tight bound check: warp w handles rows w, w+16 ----
    for (int r = w; r < 32; r += 16) {
        int grow = m0 + r;
        float accu = 0.0f;                 // lane = timestep
        for (int ch = 0; ch < 13; ch++) {
            int i = ch * 32 + lane;
            unsigned word = (i < H1) ? stage_u[r * SBST + i] : 0u;
            unsigned bal = __ballot_sync(0xffffffffu, word != 0u);
            while (bal) {
                int b = __ffs(bal) - 1;
                bal &= bal - 1;
                unsigned wb = __shfl_sync(0xffffffffu, word, b);
                float ci = s_c[ch * 32 + b];
                if ((wb >> lane) & 1u) accu += ci;
            }
        }
        float u = s_b2max + accu;
        float vb = 0.0f, vbmax = -3.4e38f;
#pragma unroll
        for (int t = 0; t < TSTEPS; t++) {
            float ut = __shfl_sync(0xffffffffu, u, t);
            vb = 0.5f * (vb + ut);
            vbmax = fmaxf(vbmax, vb);
        }
        if (vbmax < 1.0f) {
            if (lane < ADIM) {
                float o = s_const[lane] + action[(size_t)grow * ADIM + lane];
                out[(size_t)grow * ADIM + lane] = fminf(fmaxf(o, -1.0f), 1.0f);
            }
        } else if (lane == 0) {
            int p = atomicAdd(&s_nslow, 1);
            s_slow[p] = (unsigned short)r;
        }
    }
    __syncthreads();

    // ---- in-CTA exact slow path: W2 prefetched in parallel chunks ----
    int nsl = s_nslow;
    for (int sr = 0; sr < nsl; sr++) {
        int r    = s_slow[sr];
        int grow = m0 + r;

        if (tid == 0) s_any = 0;
        if (w == 0) {
            int nf = 0;
            for (int ch = 0; ch < 13; ch++) {
                int i = ch * 32 + lane;
                unsigned m = (i < H1) ? stage_u[r * SBST + i] : 0u;
                unsigned bal = __ballot_sync(0xffffffffu, m != 0u);
                int pos = nf + __popc(bal & lmask);
                if (m != 0u) { s_fire[pos] = (unsigned short)i; s_msk[pos] = m; }
                nf += __popc(bal);
            }
            if (lane == 0) s_nf = nf;
        }
        __syncthreads();
        int nf = s_nf;

        float a0[TSTEPS];
#pragma unroll
        for (int t = 0; t < TSTEPS; t++) a0[t] = 0.0f;

        for (int base = 0; base < nf; base += W2C) {
            int n = nf - base; if (n > W2C) n = W2C;
            for (int idx = tid; idx < n * H2; idx += NT) {
                int q = idx / H2;
                int j = idx - q * H2;
                s_w2c[q * H2 + j] = W2[(size_t)s_fire[base + q] * H2 + j];
            }
            __syncthreads();
            if (tid < H2) {
                for (int q = 0; q < n; q++) {
                    float wv = s_w2c[q * H2 + tid];
                    unsigned m = s_msk[base + q];
#pragma unroll
                    for (int t = 0; t < TSTEPS; t++)
                        if ((m >> t) & 1u) a0[t] += wv;
                }
            }
            __syncthreads();
        }

        if (tid < H2) {
            float b2j = b2[tid];
            float v2 = 0.0f;
            unsigned mask2 = 0u;
#pragma unroll
            for (int t = 0; t < TSTEPS; t++) {
                float x2 = b2j + a0[t];
                v2 += (x2 - v2) * 0.5f;
                if (v2 >= 1.0f) { mask2 |= (1u << t); v2 = 0.0f; }
            }
            s_mask2[tid] = mask2;
            if (mask2) atomicOr(&s_any, 1);
        }
        __syncthreads();

        if (s_any == 0) {
            if (tid < ADIM) {
                float o = s_const[tid] + action[(size_t)grow * ADIM + tid];
                out[(size_t)grow * ADIM + tid] = fminf(fmaxf(o, -1.0f), 1.0f);
            }
        } else {
            for (int t = w; t < TSTEPS; t += 16) {
                int cnt = 0;
                for (int ch = 0; ch * 32 < H2; ch++) {
                    int j = ch * 32 + lane;
                    int pred = 0;
                    if (j < H2) pred = (int)((s_mask2[j] >> t) & 1u);
                    unsigned bal = __ballot_sync(0xffffffffu, pred);
                    int pos = cnt + __popc(bal & lmask);
                    if (pred && pos < CAP2) s_list2[t][pos] = (unsigned short)j;
                    cnt += __popc(bal);
                }
                s_cnt2[t] = cnt < CAP2 ? cnt : CAP2;
            }
            __syncthreads();
            if (tid < ADIM) {
                int k = tid;
                float b3k = b3[k];
                float v3 = 0.0f, vmax = -3.4e38f;
                for (int t = 0; t < TSTEPS; t++) {
                    float x3 = b3k;
                    int n = s_cnt2[t];
                    for (int q = 0; q < n; q++)
                        x3 += W3[s_list2[t][q] * ADIM + k];
                    v3 += (x3 - v3) * 0.5f;
                    vmax = fmaxf(vmax, v3);
                }
                float a2 = 0.05f * tanhf(vmax);
                float o = a2 + action[(size_t)grow * ADIM + k];
                out[(size_t)grow * ADIM + k] = fminf(fmaxf(o, -1.0f), 1.0f);
            }
        }
        __syncthreads();
    }
}

// ---------------- launch ----------------
extern "C" void kernel_launch(void* const* d_in, const int* in_sizes, int n_in,
                              void* d_out, int out_size) {
    (void)in_sizes; (void)n_in; (void)out_size;
    const float* state  = (const float*)d_in[0];
    const float* action = (const float*)d_in[1];
    const float* W1     = (const float*)d_in[2];
    const float* b1     = (const float*)d_in[3];
    const float* W2     = (const float*)d_in[4];
    const float* b2     = (const float*)d_in[5];
    const float* W3     = (const float*)d_in[6];
    const float* b3     = (const float*)d_in[7];
    float* out = (float*)d_out;

    cudaFuncSetAttribute(k_fused, cudaFuncAttributeMaxDynamicSharedMemorySize,
                         SM_DYN);

    k_setup<<<PACKB + CBLK + 1, 256>>>(W1, W2, b2, b3);

    k_fused<<<BATCH / 32, NT, SM_DYN>>>(state, action, b1, W2, b2, W3, b3, out);
}

// round 17
// speedup vs baseline: 1.8664x; 1.0203x over previous
#include <cuda_runtime.h>
#include <cuda_bf16.h>
#include <mma.h>
#include <math.h>

using namespace nvcuda;

#define BATCH 8192
#define SDIM  376
#define ADIM  17
#define DIN   393
#define DPAD  416           // padded K: 13 chunks of 32
#define KCH   32
#define NCHK  13
#define H1    400
#define NPAD  400           // NO column padding: 25 frags of 16
#define SBST  408           // B smem stride (odd multiple of 8 -> conflict-free)
#define SAST  424           // full-K A smem stride
#define H2    300
#define TSTEPS 32
#define CAP2  96
#define W2C   22            // W2 rows cached per chunk in the in-CTA slow path
#define NT    512           // threads per CTA (16 warps)
#define SPCAP 2048          // spike-candidate list capacity (exp ~512)

// smem layout (dynamic): [A 32*424*2 = 27136][B0 26112][B1 26112] = 79360
// epilogue overlay: fp32 stage [0, 52224) ; W2 cache [52224, 78624)
#define SM_A     0
#define SM_B0    27136
#define SM_B1    (27136 + 26112)
#define SM_DYN   (27136 + 2 * 26112)
#define SM_STAGE_BYTES (32 * SBST * 4)     // 52224
#define SM_W2C   SM_STAGE_BYTES

// setup-kernel grid split
#define PACKN   (DPAD * NPAD)              // 166400 elements
#define PACKB   ((PACKN + 1023) / 1024)    // 163 blocks pack W1 (4 elems/thread)
#define CBLK    ((H1 + 7) / 8)             // 50 blocks compute c_i (warp/row)

// ---------------- static device scratch ----------------
__device__ __align__(16) __nv_bfloat16 g_W1p[(size_t)DPAD * NPAD];
__device__ float g_c[H1];          // c_i = max_j W2[i,j]
__device__ float g_b2max;
__device__ float g_const[ADIM];    // 0.05*tanh(vmax(b3_k))

// ---------------- cp.async helpers ----------------
__device__ __forceinline__ void cp16(void* dst, const void* src) {
    unsigned d = (unsigned)__cvta_generic_to_shared(dst);
    asm volatile("cp.async.cg.shared.global [%0], [%1], 16;\n" :: "r"(d), "l"(src));
}
__device__ __forceinline__ void cp_commit() {
    asm volatile("cp.async.commit_group;\n");
}
template<int N> __device__ __forceinline__ void cp_wait() {
    asm volatile("cp.async.wait_group %0;\n" :: "n"(N));
}

// ---------------- K_setup: pack W1 + constants (one launch) ----------------
__global__ __launch_bounds__(256) void k_setup(const float* __restrict__ W1,
                                               const float* __restrict__ W2,
                                               const float* __restrict__ b2,
                                               const float* __restrict__ b3) {
    int bid = blockIdx.x;
    int tid = threadIdx.x;
    if (bid < PACKB) {
        int e0 = (bid * 256 + tid) * 4;
        if (e0 < PACKN) {                    // NPAD==H1: all cols valid
            int r = e0 / NPAD;
            int c = e0 - r * NPAD;           // 400 % 4 == 0: no row crossing
            __nv_bfloat16 v[4];
            if (r < DIN) {
                float4 f = *reinterpret_cast<const float4*>(&W1[(size_t)r * H1 + c]);
                v[0] = __float2bfloat16(f.x); v[1] = __float2bfloat16(f.y);
                v[2] = __float2bfloat16(f.z); v[3] = __float2bfloat16(f.w);
            } else {
                v[0] = v[1] = v[2] = v[3] = __float2bfloat16(0.0f);
            }
            *reinterpret_cast<uint2*>(&g_W1p[e0]) = *reinterpret_cast<uint2*>(v);
        }
        return;
    }
    int lane = tid & 31;
    int w    = tid >> 5;
    if (bid < PACKB + CBLK) {
        int i = (bid - PACKB) * 8 + w;     // one warp per neuron row
        if (i < H1) {
            float mm0 = -3.4e38f, mm1 = -3.4e38f, mm2 = -3.4e38f, mm3 = -3.4e38f;
            const float* row = &W2[(size_t)i * H2];
            int j = lane;
#pragma unroll
            for (int k = 0; k < 2; k++) {
                if (j < H2) mm0 = fmaxf(mm0, row[j]); j += 32;
                if (j < H2) mm1 = fmaxf(mm1, row[j]); j += 32;
                if (j < H2) mm2 = fmaxf(mm2, row[j]); j += 32;
                if (j < H2) mm3 = fmaxf(mm3, row[j]); j += 32;
            }
            if (j < H2) mm0 = fmaxf(mm0, row[j]); j += 32;
            if (j < H2) mm1 = fmaxf(mm1, row[j]);
            float m = fmaxf(fmaxf(mm0, mm1), fmaxf(mm2, mm3));
#pragma unroll
            for (int o = 16; o; o >>= 1) m = fmaxf(m, __shfl_xor_sync(0xffffffffu, m, o));
            if (lane == 0) g_c[i] = m;
        }
        return;
    }
    if (w == 0) {
        float m = -3.4e38f;
        for (int j = lane; j < H2; j += 32) m = fmaxf(m, b2[j]);
#pragma unroll
        for (int o = 16; o; o >>= 1) m = fmaxf(m, __shfl_xor_sync(0xffffffffu, m, o));
        if (lane == 0) g_b2max = m;
    } else if (w == 1) {
        if (lane < ADIM) {
            float b = b3[lane];
            float vmax = (b > 0.0f) ? b : 0.5f * b;   // monotone v3 = b3*(1-2^-t)
            g_const[lane] = 0.05f * tanhf(vmax);
        }
    }
}

// ---------------- K1: fully fused kernel (16 warps, N=400 exact) ----------
// warp w: rowgroup rg = w>>3 (16 rows), colset cw = w&7 with widths
// {4,3,3,3,3,3,3,3} frags of 16 cols => 400 cols total per rowgroup.
__global__ __launch_bounds__(NT, 2) void k_fused(const float* __restrict__ state,
                                                 const float* __restrict__ action,
                                                 const float* __restrict__ b1,
                                                 const float* __restrict__ W2,
                                                 const float* __restrict__ b2,
                                                 const float* __restrict__ W3,
                                                 const float* __restrict__ b3,
                                                 float* __restrict__ out) {
    extern __shared__ __align__(16) unsigned char sm[];
    __nv_bfloat16* sA  = reinterpret_cast<__nv_bfloat16*>(sm + SM_A);
    __nv_bfloat16* sB0 = reinterpret_cast<__nv_bfloat16*>(sm + SM_B0);
    __nv_bfloat16* sB1 = reinterpret_cast<__nv_bfloat16*>(sm + SM_B1);
    float*    stage   = reinterpret_cast<float*>(sm);           // epilogue overlay
    unsigned* stage_u = reinterpret_cast<unsigned*>(sm);
    float*    s_w2c   = reinterpret_cast<float*>(sm + SM_W2C);  // 22x300 W2 cache

    __shared__ float s_c[H1];
    __shared__ float s_b1[H1];
    __shared__ float s_const[ADIM];
    __shared__ float s_b2max;
    // spike compaction list
    __shared__ unsigned short s_spk[SPCAP];
    __shared__ int            s_nsp;
    // slow-path scratch
    __shared__ unsigned short s_fire[H1];
    __shared__ unsigned       s_msk[H1];
    __shared__ unsigned       s_mask2[H2];
    __shared__ unsigned short s_list2[TSTEPS][CAP2];
    __shared__ int            s_cnt2[TSTEPS];
    __shared__ unsigned short s_slow[32];
    __shared__ int            s_nslow, s_nf, s_any;

    const int tid  = threadIdx.x;
    const int lane = tid & 31;
    const int w    = tid >> 5;             // 0..15
    const int rg   = w >> 3;               // 0..1
    const int cw   = w & 7;                // 0..7
    const int nfr  = (cw == 0) ? 4 : 3;    // frags this warp owns
    const int fb   = (cw == 0) ? 0 : 4 + (cw - 1) * 3;   // frag base
    const int m0   = blockIdx.x * 32;
    const unsigned lmask = (1u << lane) - 1u;

    if (tid == 0) { s_nslow = 0; s_nsp = 0; }

    auto load_B = [&](int c, __nv_bfloat16* dst) {
        // 32 k-rows x 400 cols -> 1600 cp16 (4 reps, guarded)
#pragma unroll
        for (int rep = 0; rep < 4; rep++) {
            int t2 = tid + rep * NT;
            if (t2 < 1600) {
                int r = t2 / 50, p = t2 - r * 50;
                cp16(dst + r * SBST + 8 * p,
                     &g_W1p[(size_t)(c * KCH + r) * NPAD + 8 * p]);
            }
        }
    };

    load_B(0, sB0);
    cp_commit();

    for (int i = tid; i < H1; i += NT) { s_c[i] = g_c[i]; s_b1[i] = b1[i]; }
    if (tid < ADIM) s_const[tid] = g_const[tid];
    if (tid == 32)  s_b2max = g_b2max;

    // A: load fp32 state/action, convert to bf16 smem (32 x 416, stride 424)
    for (int idx = tid; idx < 32 * SDIM; idx += NT) {
        int r = idx / SDIM, c = idx - r * SDIM;
        sA[r * SAST + c] = __float2bfloat16(state[(size_t)(m0 + r) * SDIM + c]);
    }
    for (int idx = tid; idx < 32 * ADIM; idx += NT) {
        int r = idx / ADIM, c = idx - r * ADIM;
        sA[r * SAST + SDIM + c] = __float2bfloat16(action[(size_t)(m0 + r) * ADIM + c]);
    }
    for (int idx = tid; idx < 32 * (DPAD - DIN); idx += NT) {
        int r = idx / (DPAD - DIN), c = idx - r * (DPAD - DIN);
        sA[r * SAST + DIN + c] = __float2bfloat16(0.0f);
    }

    wmma::fragment<wmma::accumulator, 16, 16, 16, float> acc[4];
#pragma unroll
    for (int f = 0; f < 4; f++) wmma::fill_fragment(acc[f], 0.0f);

    // ---- single-sync mainloop ----
    for (int c = 0; c < NCHK; c++) {
        __nv_bfloat16* cur = (c & 1) ? sB1 : sB0;
        __nv_bfloat16* nxt = (c & 1) ? sB0 : sB1;
        cp_wait<0>();
        __syncthreads();
        if (c + 1 < NCHK) {
            load_B(c + 1, nxt);
            cp_commit();
        }
#pragma unroll
        for (int ks = 0; ks < 2; ks++) {
            wmma::fragment<wmma::matrix_a, 16, 16, 16, __nv_bfloat16, wmma::row_major> afrag;
            wmma::load_matrix_sync(afrag,
                sA + (rg * 16) * SAST + c * KCH + ks * 16, SAST);
#pragma unroll
            for (int f = 0; f < 4; f++) {
                if (f < nfr) {
                    wmma::fragment<wmma::matrix_b, 16, 16, 16, __nv_bfloat16, wmma::row_major> bfrag;
                    wmma::load_matrix_sync(bfrag,
                        cur + (ks * 16) * SBST + (fb + f) * 16, SBST);
                    wmma::mma_sync(acc[f], afrag, bfrag, acc[f]);
                }
            }
        }
    }
    __syncthreads();                 // all mma done before stage overlay

    // ---- epilogue: stage fp32 (overlay) ----
#pragma unroll
    for (int f = 0; f < 4; f++)
        if (f < nfr)
            wmma::store_matrix_sync(&stage[(rg * 16) * SBST + (fb + f) * 16],
                                    acc[f], SBST, wmma::mem_row_major);
    __syncthreads();

    // ---- LIF pass 1: zero non-spiking words, compact spiking candidates ----
    for (int it = 0; it < (32 * H1 + NT - 1) / NT; it++) {
        int idx = tid + it * NT;
        bool valid = idx < 32 * H1;
        int sidx = 0;
        float x = 0.0f;
        if (valid) {
            int r = idx / H1;
            int c = idx - r * H1;
            sidx = r * SBST + c;
            x = stage[sidx] + s_b1[c];
        }
        bool sp = valid && (x >= 0.999999f);   // v_t < x: x<1 can't spike
        unsigned bal = __ballot_sync(0xffffffffu, sp);
        if (bal) {
            int ldr = __ffs(bal) - 1;
            int base;
            if (lane == ldr) base = atomicAdd(&s_nsp, __popc(bal));
            base = __shfl_sync(0xffffffffu, base, ldr);
            if (sp) {
                int pos = base + __popc(bal & lmask);
                if (pos < SPCAP) {
                    s_spk[pos] = (unsigned short)sidx;   // sidx < 13056 fits
                } else {
                    float v = 0.0f; unsigned word = 0u;
#pragma unroll
                    for (int t = 0; t < TSTEPS; t++) {
                        v = fmaf(x - v, 0.5f, v);
                        if (v >= 1.0f) { word |= (1u << t); v = 0.0f; }
                    }
                    stage_u[sidx] = word;
                }
            }
        }
        if (valid && !sp) stage_u[sidx] = 0u;
    }
    __syncthreads();

    // ---- LIF pass 2: dense 32-step simulation of compacted list ----
    {
        int nsp = s_nsp < SPCAP ? s_nsp : SPCAP;
        for (int i = tid; i < nsp; i += NT) {
            int sidx = s_spk[i];
            int r = sidx / SBST;
            int c = sidx - r * SBST;
            float x = stage[sidx] + s_b1[c];
            float v = 0.0f; unsigned word = 0u;
#pragma unroll
            for (int t = 0; t < TSTEPS; t++) {
                v = fmaf(x - v, 0.5f, v);
                if (v >= 1.0f) { word |= (1u << t); v = 0.0f; }
            }
            stage_u[sidx] = word;
        }
    }
    __syncthreads();

    // ---- per-row tight bound check: warp w handles rows w, w+16 ----
    for (int r = w; r < 32; r += 16) {
        int grow = m0 + r;
        float accu = 0.0f;                 // lane = timestep
        for (int ch = 0; ch < 13; ch++) {
            int i = ch * 32 + lane;
            unsigned word = (i < H1) ? stage_u[r * SBST + i] : 0u;
            unsigned bal = __ballot_sync(0xffffffffu, word != 0u);
            while (bal) {
                int b = __ffs(bal) - 1;
                bal &= bal - 1;
                unsigned wb = __shfl_sync(0xffffffffu, word, b);
                float ci = s_c[ch * 32 + b];
                if ((wb >> lane) & 1u) accu += ci;
            }
        }
        float u = s_b2max + accu;
        float vb = 0.0f, vbmax = -3.4e38f;
#pragma unroll
        for (int t = 0; t < TSTEPS; t++) {
            float ut = __shfl_sync(0xffffffffu, u, t);
            vb = 0.5f * (vb + ut);
            vbmax = fmaxf(vbmax, vb);
        }
        if (vbmax < 1.0f) {
            if (lane < ADIM) {
                float o = s_const[lane] + action[(size_t)grow * ADIM + lane];
                out[(size_t)grow * ADIM + lane] = fminf(fmaxf(o, -1.0f), 1.0f);
            }
        } else if (lane == 0) {
            int p = atomicAdd(&s_nslow, 1);
            s_slow[p] = (unsigned short)r;
        }
    }
    __syncthreads();

    // ---- in-CTA exact slow path: W2 prefetched in parallel chunks ----
    int nsl = s_nslow;
    for (int sr = 0; sr < nsl; sr++) {
        int r    = s_slow[sr];
        int grow = m0 + r;

        if (tid == 0) s_any = 0;
        if (w == 0) {
            int nf = 0;
            for (int ch = 0; ch < 13; ch++) {
                int i = ch * 32 + lane;
                unsigned m = (i < H1) ? stage_u[r * SBST + i] : 0u;
                unsigned bal = __ballot_sync(0xffffffffu, m != 0u);
                int pos = nf + __popc(bal & lmask);
                if (m != 0u) { s_fire[pos] = (unsigned short)i; s_msk[pos] = m; }
                nf += __popc(bal);
            }
            if (lane == 0) s_nf = nf;
        }
        __syncthreads();
        int nf = s_nf;

        float a0[TSTEPS];
#pragma unroll
        for (int t = 0; t < TSTEPS; t++) a0[t] = 0.0f;

        for (int base = 0; base < nf; base += W2C) {
            int n = nf - base; if (n > W2C) n = W2C;
            for (int idx = tid; idx < n * H2; idx += NT) {
                int q = idx / H2;
                int j = idx - q * H2;
                s_w2c[q * H2 + j] = W2[(size_t)s_fire[base + q] * H2 + j];
            }
            __syncthreads();
            if (tid < H2) {
                for (int q = 0; q < n; q++) {
                    float wv = s_w2c[q * H2 + tid];
                    unsigned m = s_msk[base + q];
#pragma unroll
                    for (int t = 0; t < TSTEPS; t++)
                        if ((m >> t) & 1u) a0[t] += wv;
                }
            }
            __syncthreads();
        }

        if (tid < H2) {
            float b2j = b2[tid];
            float v2 = 0.0f;
            unsigned mask2 = 0u;
#pragma unroll
            for (int t = 0; t < TSTEPS; t++) {
                float x2 = b2j + a0[t];
                v2 += (x2 - v2) * 0.5f;
                if (v2 >= 1.0f) { mask2 |= (1u << t); v2 = 0.0f; }
            }
            s_mask2[tid] = mask2;
            if (mask2) atomicOr(&s_any, 1);
        }
        __syncthreads();

        if (s_any == 0) {
            if (tid < ADIM) {
                float o = s_const[tid] + action[(size_t)grow * ADIM + tid];
                out[(size_t)grow * ADIM + tid] = fminf(fmaxf(o, -1.0f), 1.0f);
            }
        } else {
            for (int t = w; t < TSTEPS; t += 16) {
                int cnt = 0;
                for (int ch = 0; ch * 32 < H2; ch++) {
                    int j = ch * 32 + lane;
                    int pred = 0;
                    if (j < H2) pred = (int)((s_mask2[j] >> t) & 1u);
                    unsigned bal = __ballot_sync(0xffffffffu, pred);
                    int pos = cnt + __popc(bal & lmask);
                    if (pred && pos < CAP2) s_list2[t][pos] = (unsigned short)j;
                    cnt += __popc(bal);
                }
                s_cnt2[t] = cnt < CAP2 ? cnt : CAP2;
            }
            __syncthreads();
            if (tid < ADIM) {
                int k = tid;
                float b3k = b3[k];
                float v3 = 0.0f, vmax = -3.4e38f;
                for (int t = 0; t < TSTEPS; t++) {
                    float x3 = b3k;
                    int n = s_cnt2[t];
                    for (int q = 0; q < n; q++)
                        x3 += W3[s_list2[t][q] * ADIM + k];
                    v3 += (x3 - v3) * 0.5f;
                    vmax = fmaxf(vmax, v3);
                }
                float a2 = 0.05f * tanhf(vmax);
                float o = a2 + action[(size_t)grow * ADIM + k];
                out[(size_t)grow * ADIM + k] = fminf(fmaxf(o, -1.0f), 1.0f);
            }
        }
        __syncthreads();
    }
}

// ---------------- launch ----------------
extern "C" void kernel_launch(void* const* d_in, const int* in_sizes, int n_in,
                              void* d_out, int out_size) {
    (void)in_sizes; (void)n_in; (void)out_size;
    const float* state  = (const float*)d_in[0];
    const float* action = (const float*)d_in[1];
    const float* W1     = (const float*)d_in[2];
    const float* b1     = (const float*)d_in[3];
    const float* W2     = (const float*)d_in[4];
    const float* b2     = (const float*)d_in[5];
    const float* W3     = (const float*)d_in[6];
    const float* b3     = (const float*)d_in[7];
    float* out = (float*)d_out;

    cudaFuncSetAttribute(k_fused, cudaFuncAttributeMaxDynamicSharedMemorySize,
                         SM_DYN);

    k_setup<<<PACKB + CBLK + 1, 256>>>(W1, W2, b2, b3);

    k_fused<<<BATCH / 32, NT, SM_DYN>>>(state, action, b1, W2, b2, W3, b3, out);
}